// round 6
// baseline (speedup 1.0000x reference)
#include <cuda_runtime.h>
#include <math.h>

#define NB 512
#define NROUTE 1152
#define NCLS 10

// ---------------- scratch ----------------------------------------------------
__device__ float g_h[NB * 256 * 400];    // conv1 out [B,256,20,20]
__device__ float g_wT[256 * 81 * 256];   // prim_w transposed [(ic*81+tap)*256+oc]
__device__ float g_p[NB * 256 * 36];     // conv2 out [B,256,6,6]
__device__ float g_u[NB * NROUTE * 8];   // squashed primary caps [B,1152,8]
__device__ float g_v[NCLS * NB * 16];    // routed outputs [C,B,16]

// ---------------- packed f32x2 (exact fp32, 2x FFMA rate) --------------------
__device__ __forceinline__ unsigned long long pack2(float a, float b) {
    unsigned long long r;
    asm("mov.b64 %0, {%1, %2};" : "=l"(r) : "f"(a), "f"(b));
    return r;
}
__device__ __forceinline__ unsigned long long fma2(unsigned long long a,
                                                   unsigned long long b,
                                                   unsigned long long c) {
    unsigned long long d;
    asm("fma.rn.f32x2 %0, %1, %2, %3;" : "=l"(d) : "l"(a), "l"(b), "l"(c));
    return d;
}
__device__ __forceinline__ float2 unpack2(unsigned long long v) {
    float2 f;
    asm("mov.b64 {%0, %1}, %2;" : "=f"(f.x), "=f"(f.y) : "l"(v));
    return f;
}

// ---------------- K0: transpose prim_w ---------------------------------------
__global__ void k_wT(const float* __restrict__ w) {
    int idx = blockIdx.x * 256 + threadIdx.x;    // 256*81*256 exact
    int oc = idx & 255;
    int rest = idx >> 8;
    int tap = rest % 81;
    int ic = rest / 81;
    g_wT[idx] = w[(oc * 256 + ic) * 81 + tap];
}

// ---------------- K1: conv1 9x9 s1 + relu ------------------------------------
__global__ void __launch_bounds__(256) k_conv1(const float* __restrict__ x,
                                               const float* __restrict__ w,
                                               const float* __restrict__ bias) {
    __shared__ float xs[784];
    int b = blockIdx.x, t = threadIdx.x;
    for (int j = t; j < 784; j += 256) xs[j] = x[b * 784 + j];
    __syncthreads();
    int oc = t;
    const float* wo = w + oc * 81;
    float bv = bias[oc];
    float* ho = g_h + (b * 256 + oc) * 400;
#pragma unroll 1
    for (int orow = 0; orow < 20; orow++) {
        float acc[20];
#pragma unroll
        for (int i = 0; i < 20; i++) acc[i] = 0.f;
#pragma unroll 1
        for (int ky = 0; ky < 9; ky++) {
            const float* xrp = xs + (orow + ky) * 28;
            float xr[28];
#pragma unroll
            for (int i = 0; i < 28; i++) xr[i] = xrp[i];
#pragma unroll
            for (int kx = 0; kx < 9; kx++) {
                float wv = wo[ky * 9 + kx];
#pragma unroll
                for (int ox = 0; ox < 20; ox++)
                    acc[ox] = fmaf(wv, xr[ox + kx], acc[ox]);
            }
        }
#pragma unroll
        for (int ox = 0; ox < 20; ox++) {
            float v = acc[ox] + bv;
            ho[orow * 20 + ox] = v > 0.f ? v : 0.f;
        }
    }
}

// ---------------- K2: primary-caps conv 9x9 s2 (f32x2) -----------------------
// 256 thr: pr = tid&127 -> oc pair (2pr,2pr+1); half = tid>>7 -> rows 3h..3h+2
__global__ void __launch_bounds__(256) k_conv2(const float* __restrict__ bias) {
    __shared__ float hs[400];
    int b = blockIdx.x, t = threadIdx.x;
    int pr = t & 127;
    int r0 = (t >> 7) * 3;
    unsigned long long acc[18];
#pragma unroll
    for (int i = 0; i < 18; i++) acc[i] = 0ull;

    const float* hb = g_h + b * 256 * 400;
#pragma unroll 1
    for (int ic = 0; ic < 256; ic++) {
        __syncthreads();
        for (int j = t; j < 400; j += 256) hs[j] = hb[ic * 400 + j];
        __syncthreads();
        const unsigned long long* wp =
            (const unsigned long long*)(g_wT + ic * 81 * 256) + pr;
#pragma unroll 1
        for (int ky = 0; ky < 9; ky++) {
            unsigned long long wv[9];
#pragma unroll
            for (int kx = 0; kx < 9; kx++) wv[kx] = wp[(ky * 9 + kx) * 128];
#pragma unroll
            for (int rr = 0; rr < 3; rr++) {
                int y = 2 * (r0 + rr) + ky;
                const float* hr = hs + y * 20;
                unsigned long long hp[20];
#pragma unroll
                for (int i = 0; i < 20; i++) {
                    float v = hr[i];
                    hp[i] = pack2(v, v);
                }
#pragma unroll
                for (int kx = 0; kx < 9; kx++)
#pragma unroll
                    for (int ox = 0; ox < 6; ox++)
                        acc[rr * 6 + ox] =
                            fma2(wv[kx], hp[2 * ox + kx], acc[rr * 6 + ox]);
            }
        }
    }
    float* pout = g_p + b * 9216;
    int oc0 = 2 * pr;
    float b0 = bias[oc0], b1 = bias[oc0 + 1];
#pragma unroll
    for (int rr = 0; rr < 3; rr++)
#pragma unroll
        for (int ox = 0; ox < 6; ox++) {
            float2 v = unpack2(acc[rr * 6 + ox]);
            int s = (r0 + rr) * 6 + ox;
            pout[oc0 * 36 + s] = v.x + b0;
            pout[(oc0 + 1) * 36 + s] = v.y + b1;
        }
}

// ---------------- K3: gather + squash primary capsules -----------------------
__global__ void k_squash(void) {
    int idx = blockIdx.x * 128 + threadIdx.x;   // NB*NROUTE exact
    int b = idx / NROUTE;
    int n = idx - b * NROUTE;
    int c = n / 36;
    int s = n - c * 36;
    const float* pb = g_p + b * 9216;
    float tv[8], sn = 0.f;
#pragma unroll
    for (int g = 0; g < 8; g++) {
        tv[g] = pb[(g * 32 + c) * 36 + s];
        sn = fmaf(tv[g], tv[g], sn);
    }
    float scale = sn / ((1.f + sn) * sqrtf(sn));
    float* up = g_u + idx * 8;
#pragma unroll
    for (int g = 0; g < 8; g++) up[g] = tv[g] * scale;
}

// ---------------- K4: priors + 3-iter dynamic routing (fused) ----------------
// grid (10, 512): block = (class c, batch b). dyn smem:
// pri[18432] | logits[1152] | probs[1152] | red[4096]
__global__ void __launch_bounds__(256) k_route(const float* __restrict__ rw_all) {
    extern __shared__ float sm[];
    float* pri = sm;
    float* logits = sm + 18432;
    float* probs = logits + 1152;
    float* red = probs + 1152;
    __shared__ float wb[8];

    int c = blockIdx.x, b = blockIdx.y, t = threadIdx.x;
    int lane = t & 31, wid = t >> 5;
    const float* ub = g_u + b * (NROUTE * 8);
    const float* rw = rw_all + c * (NROUTE * 128);

    for (int j = t; j < 18432; j += 256) {
        int n = j >> 4, o = j & 15;
        const float* up = ub + n * 8;
        const float* rp = rw + n * 128 + o;
        float s = 0.f;
#pragma unroll
        for (int i = 0; i < 8; i++) s = fmaf(up[i], rp[i * 16], s);
        pri[j] = s;
    }
    for (int j = t; j < 1152; j += 256) logits[j] = 0.f;
    __syncthreads();

    for (int it = 0; it < 3; it++) {
        // softmax over n (each thread owns n == t mod 256)
        float lm = -1e30f;
        for (int n = t; n < 1152; n += 256) lm = fmaxf(lm, logits[n]);
#pragma unroll
        for (int off = 16; off > 0; off >>= 1)
            lm = fmaxf(lm, __shfl_xor_sync(0xffffffffu, lm, off));
        if (lane == 0) wb[wid] = lm;
        __syncthreads();
        float m = wb[0];
#pragma unroll
        for (int k = 1; k < 8; k++) m = fmaxf(m, wb[k]);
        __syncthreads();

        float ls = 0.f;
        for (int n = t; n < 1152; n += 256) {
            float e = __expf(logits[n] - m);
            probs[n] = e;
            ls += e;
        }
#pragma unroll
        for (int off = 16; off > 0; off >>= 1)
            ls += __shfl_xor_sync(0xffffffffu, ls, off);
        if (lane == 0) wb[wid] = ls;
        __syncthreads();
        float Z = 0.f;
#pragma unroll
        for (int k = 0; k < 8; k++) Z += wb[k];
        float inv = 1.f / Z;

        // s[o] = sum_n probs[n]*pri[n][o]
        float a16[16];
#pragma unroll
        for (int o = 0; o < 16; o++) a16[o] = 0.f;
        for (int n = t; n < 1152; n += 256) {
            float ps = probs[n] * inv;
            const float* pp = pri + n * 16;
#pragma unroll
            for (int o = 0; o < 16; o++) a16[o] = fmaf(ps, pp[o], a16[o]);
        }
        __syncthreads();   // red free for reuse
#pragma unroll
        for (int o = 0; o < 16; o++) red[t * 16 + o] = a16[o];
        __syncthreads();
        for (int st = 128; st > 0; st >>= 1) {
            if (t < st)
#pragma unroll
                for (int o = 0; o < 16; o++)
                    red[t * 16 + o] += red[(t + st) * 16 + o];
            __syncthreads();
        }
        // squash(s): red[0..15] = s
        float sn = 0.f;
#pragma unroll
        for (int o = 0; o < 16; o++) sn = fmaf(red[o], red[o], sn);
        float scale = sn / ((1.f + sn) * sqrtf(sn));

        if (it < 2) {
            for (int n = t; n < 1152; n += 256) {
                const float* pp = pri + n * 16;
                float d = 0.f;
#pragma unroll
                for (int o = 0; o < 16; o++) d = fmaf(pp[o], red[o], d);
                logits[n] += d * scale;
            }
        } else {
            if (t < 16) g_v[(c * NB + b) * 16 + t] = red[t] * scale;
        }
        __syncthreads();
    }
}

// ---------------- K5: classes/argmax/mask + decoder MLP ----------------------
// 64 blocks x 256 thr, 8 batches per block. dyn smem:
// h1[8*512] | h2[8*1024] | vcap[8*16] | cl[8*10]
__global__ void __launch_bounds__(256) k_dec(
    const float* __restrict__ w1, const float* __restrict__ b1,
    const float* __restrict__ w2, const float* __restrict__ b2,
    const float* __restrict__ w3, const float* __restrict__ b3,
    float* __restrict__ out) {
    extern __shared__ float sm[];
    float* h1 = sm;                 // 4096
    float* h2 = sm + 4096;          // 8192
    float* vcap = h2 + 8192;        // 128
    float* cl = vcap + 128;         // 80
    __shared__ int cls[8];

    int t = threadIdx.x;
    int b0 = blockIdx.x * 8;
    const int RECON_OFF = NB * NCLS;               // 5120
    const int CLS_OFF = RECON_OFF + NB * 784;      // 406528

    if (t < 80) {
        int bb = t / 10, c = t - bb * 10;
        const float* vp = g_v + (c * NB + b0 + bb) * 16;
        float sn = 0.f;
#pragma unroll
        for (int o = 0; o < 16; o++) sn = fmaf(vp[o], vp[o], sn);
        float nv = sqrtf(sn);
        cl[bb * 10 + c] = nv;
        out[CLS_OFF + (b0 + bb) * 10 + c] = nv;
    }
    __syncthreads();
    if (t < 8) {
        float m = -1e30f;
        int idx = 0;
        for (int c = 0; c < 10; c++) {
            float v = cl[t * 10 + c];
            if (v > m) { m = v; idx = c; }
        }
        cls[t] = idx;
    }
    __syncthreads();
    if (t < 80) {
        int bb = t / 10, c = t - bb * 10;
        out[(b0 + bb) * 10 + c] = (c == cls[bb]) ? 1.f : 0.f;
    }
    if (t < 128) {
        int bb = t >> 4, o = t & 15;
        vcap[t] = g_v[(cls[bb] * NB + b0 + bb) * 16 + o];
    }
    __syncthreads();

    // d1: 160->512 (sparse: 16 active rows per batch)
#pragma unroll
    for (int jj = 0; jj < 2; jj++) {
        int j = t + jj * 256;
        float a[8];
        float bv = b1[j];
#pragma unroll
        for (int bb = 0; bb < 8; bb++) a[bb] = bv;
#pragma unroll 1
        for (int bb = 0; bb < 8; bb++) {
            const float* wr = w1 + (cls[bb] * 16) * 512 + j;
#pragma unroll
            for (int o = 0; o < 16; o++)
                a[bb] = fmaf(vcap[bb * 16 + o], wr[o * 512], a[bb]);
        }
#pragma unroll
        for (int bb = 0; bb < 8; bb++)
            h1[bb * 512 + j] = a[bb] > 0.f ? a[bb] : 0.f;
    }
    __syncthreads();

    // d2: 512->1024
#pragma unroll 1
    for (int jj = 0; jj < 4; jj++) {
        int j = t + jj * 256;
        float a[8];
        float bv = b2[j];
#pragma unroll
        for (int bb = 0; bb < 8; bb++) a[bb] = bv;
#pragma unroll 4
        for (int k = 0; k < 512; k++) {
            float wv = w2[k * 1024 + j];
#pragma unroll
            for (int bb = 0; bb < 8; bb++)
                a[bb] = fmaf(wv, h1[bb * 512 + k], a[bb]);
        }
#pragma unroll
        for (int bb = 0; bb < 8; bb++)
            h2[bb * 1024 + j] = a[bb] > 0.f ? a[bb] : 0.f;
    }
    __syncthreads();

    // d3: 1024->784 + sigmoid
#pragma unroll 1
    for (int j = t; j < 784; j += 256) {
        float a[8];
        float bv = b3[j];
#pragma unroll
        for (int bb = 0; bb < 8; bb++) a[bb] = bv;
#pragma unroll 4
        for (int k = 0; k < 1024; k++) {
            float wv = w3[k * 784 + j];
#pragma unroll
            for (int bb = 0; bb < 8; bb++)
                a[bb] = fmaf(wv, h2[bb * 1024 + k], a[bb]);
        }
#pragma unroll
        for (int bb = 0; bb < 8; bb++)
            out[RECON_OFF + (b0 + bb) * 784 + j] = 1.f / (1.f + expf(-a[bb]));
    }
}

// ---------------- launch -----------------------------------------------------
extern "C" void kernel_launch(void* const* d_in, const int* in_sizes, int n_in,
                              void* d_out, int out_size) {
    const float* x = (const float*)d_in[0];
    const float* conv1_w = (const float*)d_in[1];
    const float* conv1_b = (const float*)d_in[2];
    const float* prim_w = (const float*)d_in[3];
    const float* prim_b = (const float*)d_in[4];
    const float* route_w = (const float*)d_in[5];
    const float* dec_w1 = (const float*)d_in[6];
    const float* dec_b1 = (const float*)d_in[7];
    const float* dec_w2 = (const float*)d_in[8];
    const float* dec_b2 = (const float*)d_in[9];
    const float* dec_w3 = (const float*)d_in[10];
    const float* dec_b3 = (const float*)d_in[11];
    float* out = (float*)d_out;

    const int SM_ROUTE = 24832 * sizeof(float);   // 99328
    const int SM_DEC = 12496 * sizeof(float);     // 49984
    cudaFuncSetAttribute(k_route, cudaFuncAttributeMaxDynamicSharedMemorySize,
                         SM_ROUTE);
    cudaFuncSetAttribute(k_dec, cudaFuncAttributeMaxDynamicSharedMemorySize,
                         SM_DEC);

    k_wT<<<(256 * 81 * 256) / 256, 256>>>(prim_w);
    k_conv1<<<NB, 256>>>(x, conv1_w, conv1_b);
    k_conv2<<<NB, 256>>>(prim_b);
    k_squash<<<(NB * NROUTE) / 128, 128>>>();
    k_route<<<dim3(NCLS, NB), 256, SM_ROUTE>>>(route_w);
    k_dec<<<NB / 8, 256, SM_DEC>>>(dec_w1, dec_b1, dec_w2, dec_b2, dec_w3,
                                   dec_b3, out);
}

// round 8
// speedup vs baseline: 1.0660x; 1.0660x over previous
#include <cuda_runtime.h>
#include <math.h>

#define NB 512
#define NROUTE 1152
#define NCLS 10

// ---------------- scratch ----------------------------------------------------
__device__ float g_h[NB * 256 * 400];    // conv1 out [B,256,20,20]
__device__ float g_wT[256 * 81 * 256];   // prim_w transposed [(ic*81+tap)*256+oc]
__device__ float g_p[NB * 256 * 36];     // conv2 out [B,256,6,6]
__device__ float g_u[NB * NROUTE * 8];   // squashed primary caps [B,1152,8]
__device__ float g_v[NCLS * NB * 16];    // routed outputs [C,B,16]

// ---------------- packed f32x2 (exact fp32, 2x FFMA rate) --------------------
__device__ __forceinline__ unsigned long long pack2(float a, float b) {
    unsigned long long r;
    asm("mov.b64 %0, {%1, %2};" : "=l"(r) : "f"(a), "f"(b));
    return r;
}
__device__ __forceinline__ unsigned long long fma2(unsigned long long a,
                                                   unsigned long long b,
                                                   unsigned long long c) {
    unsigned long long d;
    asm("fma.rn.f32x2 %0, %1, %2, %3;" : "=l"(d) : "l"(a), "l"(b), "l"(c));
    return d;
}
__device__ __forceinline__ float2 unpack2(unsigned long long v) {
    float2 f;
    asm("mov.b64 {%0, %1}, %2;" : "=f"(f.x), "=f"(f.y) : "l"(v));
    return f;
}

// ---------------- K0: transpose prim_w ---------------------------------------
__global__ void k_wT(const float* __restrict__ w) {
    int idx = blockIdx.x * 256 + threadIdx.x;    // 256*81*256 exact
    int oc = idx & 255;
    int rest = idx >> 8;
    int tap = rest % 81;
    int ic = rest / 81;
    g_wT[idx] = w[(oc * 256 + ic) * 81 + tap];
}

// ---------------- K1: conv1 9x9 s1 + relu ------------------------------------
__global__ void __launch_bounds__(256) k_conv1(const float* __restrict__ x,
                                               const float* __restrict__ w,
                                               const float* __restrict__ bias) {
    __shared__ float xs[784];
    int b = blockIdx.x, t = threadIdx.x;
    for (int j = t; j < 784; j += 256) xs[j] = x[b * 784 + j];
    __syncthreads();
    int oc = t;
    const float* wo = w + oc * 81;
    float bv = bias[oc];
    float* ho = g_h + (b * 256 + oc) * 400;
#pragma unroll 1
    for (int orow = 0; orow < 20; orow++) {
        float acc[20];
#pragma unroll
        for (int i = 0; i < 20; i++) acc[i] = 0.f;
#pragma unroll 1
        for (int ky = 0; ky < 9; ky++) {
            const float* xrp = xs + (orow + ky) * 28;
            float xr[28];
#pragma unroll
            for (int i = 0; i < 28; i++) xr[i] = xrp[i];
#pragma unroll
            for (int kx = 0; kx < 9; kx++) {
                float wv = wo[ky * 9 + kx];
#pragma unroll
                for (int ox = 0; ox < 20; ox++)
                    acc[ox] = fmaf(wv, xr[ox + kx], acc[ox]);
            }
        }
#pragma unroll
        for (int ox = 0; ox < 20; ox++) {
            float v = acc[ox] + bv;
            ho[orow * 20 + ox] = v > 0.f ? v : 0.f;
        }
    }
}

// ---------------- K2: primary-caps conv 9x9 s2 (f32x2, pipelined) ------------
// 256 thr: pr = tid&127 -> oc pair (2pr,2pr+1); half = tid>>7 -> rows 3h..3h+2
// hs: double-buffered, stored as duplicated f32x2 pairs (LDS.64 direct operand)
__global__ void __launch_bounds__(256, 2) k_conv2(const float* __restrict__ bias) {
    __shared__ unsigned long long hs[2][400];
    int b = blockIdx.x, t = threadIdx.x;
    int pr = t & 127;
    int r0 = (t >> 7) * 3;
    unsigned long long acc[18];
#pragma unroll
    for (int i = 0; i < 18; i++) acc[i] = 0ull;

    const float* hb = g_h + b * 102400;
    // preload ic=0
    float c0 = hb[t];
    float c1 = (t < 144) ? hb[256 + t] : 0.f;
    hs[0][t] = pack2(c0, c0);
    if (t < 144) hs[0][256 + t] = pack2(c1, c1);
    __syncthreads();

#pragma unroll 1
    for (int ic = 0; ic < 256; ic++) {
        int buf = ic & 1;
        // prefetch next channel (latency hidden under compute)
        if (ic < 255) {
            c0 = hb[(ic + 1) * 400 + t];
            c1 = (t < 144) ? hb[(ic + 1) * 400 + 256 + t] : 0.f;
        }
        const unsigned long long* wp =
            (const unsigned long long*)(g_wT + ic * 20736) + pr;
#pragma unroll 1
        for (int ky = 0; ky < 9; ky++) {
            unsigned long long wv[9];
#pragma unroll
            for (int kx = 0; kx < 9; kx++) wv[kx] = wp[(ky * 9 + kx) * 128];
#pragma unroll
            for (int rr = 0; rr < 3; rr++) {
                const unsigned long long* hr =
                    hs[buf] + (2 * (r0 + rr) + ky) * 20;
                unsigned long long hp[20];
#pragma unroll
                for (int i = 0; i < 20; i++) hp[i] = hr[i];
#pragma unroll
                for (int kx = 0; kx < 9; kx++)
#pragma unroll
                    for (int ox = 0; ox < 6; ox++)
                        acc[rr * 6 + ox] =
                            fma2(wv[kx], hp[2 * ox + kx], acc[rr * 6 + ox]);
            }
        }
        if (ic < 255) {
            hs[buf ^ 1][t] = pack2(c0, c0);
            if (t < 144) hs[buf ^ 1][256 + t] = pack2(c1, c1);
        }
        __syncthreads();
    }

    float* pout = g_p + b * 9216;
    int oc0 = 2 * pr;
    float b0 = bias[oc0], b1 = bias[oc0 + 1];
#pragma unroll
    for (int rr = 0; rr < 3; rr++)
#pragma unroll
        for (int ox = 0; ox < 6; ox++) {
            float2 v = unpack2(acc[rr * 6 + ox]);
            int s = (r0 + rr) * 6 + ox;
            pout[oc0 * 36 + s] = v.x + b0;
            pout[(oc0 + 1) * 36 + s] = v.y + b1;
        }
}

// ---------------- K3: gather + squash primary capsules -----------------------
__global__ void k_squash(void) {
    int idx = blockIdx.x * 128 + threadIdx.x;   // NB*NROUTE exact
    int b = idx / NROUTE;
    int n = idx - b * NROUTE;
    int c = n / 36;
    int s = n - c * 36;
    const float* pb = g_p + b * 9216;
    float tv[8], sn = 0.f;
#pragma unroll
    for (int g = 0; g < 8; g++) {
        tv[g] = pb[(g * 32 + c) * 36 + s];
        sn = fmaf(tv[g], tv[g], sn);
    }
    float scale = sn / ((1.f + sn) * sqrtf(sn));
    float* up = g_u + idx * 8;
#pragma unroll
    for (int g = 0; g < 8; g++) up[g] = tv[g] * scale;
}

// ---------------- K4: priors + 3-iter dynamic routing (fused) ----------------
// grid (10, 512). dyn smem: pri[1152*17] | logits[1152] | probs[1152] | red[256]
__global__ void __launch_bounds__(256) k_route(const float* __restrict__ rw_all) {
    extern __shared__ float sm[];
    float* pri = sm;                    // 19584 (stride 17: bank-conflict-free)
    float* logits = pri + 19584;        // 1152
    float* probs = logits + 1152;       // 1152
    float* red = probs + 1152;          // 256
    __shared__ float wb[8];
    __shared__ float sbuf[17];          // s[0..15], scale at [16]

    int c = blockIdx.x, b = blockIdx.y, t = threadIdx.x;
    int lane = t & 31, wid = t >> 5;
    const float* ub = g_u + b * (NROUTE * 8);
    const float* rw = rw_all + c * (NROUTE * 128);

    for (int j = t; j < 18432; j += 256) {
        int n = j >> 4, o = j & 15;
        const float* up = ub + n * 8;
        const float* rp = rw + n * 128 + o;
        float s = 0.f;
#pragma unroll
        for (int i = 0; i < 8; i++) s = fmaf(up[i], rp[i * 16], s);
        pri[n * 17 + o] = s;
    }
    for (int j = t; j < 1152; j += 256) logits[j] = 0.f;
    __syncthreads();

    int oo = t & 15, sl = t >> 4;

    for (int it = 0; it < 3; it++) {
        // softmax max over n
        float lm = -1e30f;
        for (int n = t; n < 1152; n += 256) lm = fmaxf(lm, logits[n]);
#pragma unroll
        for (int off = 16; off > 0; off >>= 1)
            lm = fmaxf(lm, __shfl_xor_sync(0xffffffffu, lm, off));
        if (lane == 0) wb[wid] = lm;
        __syncthreads();
        float m = wb[0];
#pragma unroll
        for (int k = 1; k < 8; k++) m = fmaxf(m, wb[k]);
        __syncthreads();

        float ls = 0.f;
        for (int n = t; n < 1152; n += 256) {
            float e = __expf(logits[n] - m);
            probs[n] = e;
            ls += e;
        }
#pragma unroll
        for (int off = 16; off > 0; off >>= 1)
            ls += __shfl_xor_sync(0xffffffffu, ls, off);
        if (lane == 0) wb[wid] = ls;
        __syncthreads();
        float Z = 0.f;
#pragma unroll
        for (int k = 0; k < 8; k++) Z += wb[k];
        float inv = 1.f / Z;

        // s[o] = inv * sum_n e[n]*pri[n][o]; thread owns (o=t&15, slice=t>>4)
        float sp = 0.f;
        for (int n = sl; n < 1152; n += 16)
            sp = fmaf(probs[n], pri[n * 17 + oo], sp);
        red[t] = sp;
        __syncthreads();
        if (t < 16) {
            float s = 0.f;
#pragma unroll
            for (int k = 0; k < 16; k++) s += red[k * 16 + t];
            sbuf[t] = s * inv;
        }
        __syncthreads();
        if (t == 0) {
            float sn = 0.f;
#pragma unroll
            for (int o = 0; o < 16; o++) sn = fmaf(sbuf[o], sbuf[o], sn);
            sbuf[16] = sn / ((1.f + sn) * sqrtf(sn));
        }
        __syncthreads();
        float scale = sbuf[16];

        if (it < 2) {
            for (int n = t; n < 1152; n += 256) {
                const float* pp = pri + n * 17;
                float d = 0.f;
#pragma unroll
                for (int o = 0; o < 16; o++) d = fmaf(pp[o], sbuf[o], d);
                logits[n] += d * scale;
            }
        } else {
            if (t < 16) g_v[(c * NB + b) * 16 + t] = sbuf[t] * scale;
        }
        __syncthreads();
    }
}

// ---------------- K5: classes/argmax/mask + decoder MLP ----------------------
// 64 blocks x 256 thr, 8 batches per block.
__global__ void __launch_bounds__(256) k_dec(
    const float* __restrict__ w1, const float* __restrict__ b1,
    const float* __restrict__ w2, const float* __restrict__ b2,
    const float* __restrict__ w3, const float* __restrict__ b3,
    float* __restrict__ out) {
    extern __shared__ float sm[];
    float* h1 = sm;                 // 4096
    float* h2 = sm + 4096;          // 8192
    float* vcap = h2 + 8192;        // 128
    float* cl = vcap + 128;         // 80
    __shared__ int cls[8];

    int t = threadIdx.x;
    int b0 = blockIdx.x * 8;
    const int RECON_OFF = NB * NCLS;               // 5120
    const int CLS_OFF = RECON_OFF + NB * 784;      // 406528

    if (t < 80) {
        int bb = t / 10, c = t - bb * 10;
        const float* vp = g_v + (c * NB + b0 + bb) * 16;
        float sn = 0.f;
#pragma unroll
        for (int o = 0; o < 16; o++) sn = fmaf(vp[o], vp[o], sn);
        float nv = sqrtf(sn);
        cl[bb * 10 + c] = nv;
        out[CLS_OFF + (b0 + bb) * 10 + c] = nv;
    }
    __syncthreads();
    if (t < 8) {
        float m = -1e30f;
        int idx = 0;
        for (int c = 0; c < 10; c++) {
            float v = cl[t * 10 + c];
            if (v > m) { m = v; idx = c; }
        }
        cls[t] = idx;
    }
    __syncthreads();
    if (t < 80) {
        int bb = t / 10, c = t - bb * 10;
        out[(b0 + bb) * 10 + c] = (c == cls[bb]) ? 1.f : 0.f;
    }
    if (t < 128) {
        int bb = t >> 4, o = t & 15;
        vcap[t] = g_v[(cls[bb] * NB + b0 + bb) * 16 + o];
    }
    __syncthreads();

    // d1: 160->512 (sparse: 16 active rows per batch)
#pragma unroll
    for (int jj = 0; jj < 2; jj++) {
        int j = t + jj * 256;
        float a[8];
        float bv = b1[j];
#pragma unroll
        for (int bb = 0; bb < 8; bb++) a[bb] = bv;
#pragma unroll 1
        for (int bb = 0; bb < 8; bb++) {
            const float* wr = w1 + (cls[bb] * 16) * 512 + j;
#pragma unroll
            for (int o = 0; o < 16; o++)
                a[bb] = fmaf(vcap[bb * 16 + o], wr[o * 512], a[bb]);
        }
#pragma unroll
        for (int bb = 0; bb < 8; bb++)
            h1[bb * 512 + j] = a[bb] > 0.f ? a[bb] : 0.f;
    }
    __syncthreads();

    // d2: 512->1024
#pragma unroll 1
    for (int jj = 0; jj < 4; jj++) {
        int j = t + jj * 256;
        float a[8];
        float bv = b2[j];
#pragma unroll
        for (int bb = 0; bb < 8; bb++) a[bb] = bv;
#pragma unroll 4
        for (int k = 0; k < 512; k++) {
            float wv = w2[k * 1024 + j];
#pragma unroll
            for (int bb = 0; bb < 8; bb++)
                a[bb] = fmaf(wv, h1[bb * 512 + k], a[bb]);
        }
#pragma unroll
        for (int bb = 0; bb < 8; bb++)
            h2[bb * 1024 + j] = a[bb] > 0.f ? a[bb] : 0.f;
    }
    __syncthreads();

    // d3: 1024->784 + sigmoid
#pragma unroll 1
    for (int j = t; j < 784; j += 256) {
        float a[8];
        float bv = b3[j];
#pragma unroll
        for (int bb = 0; bb < 8; bb++) a[bb] = bv;
#pragma unroll 4
        for (int k = 0; k < 1024; k++) {
            float wv = w3[k * 784 + j];
#pragma unroll
            for (int bb = 0; bb < 8; bb++)
                a[bb] = fmaf(wv, h2[bb * 1024 + k], a[bb]);
        }
#pragma unroll
        for (int bb = 0; bb < 8; bb++)
            out[RECON_OFF + (b0 + bb) * 784 + j] = 1.f / (1.f + expf(-a[bb]));
    }
}

// ---------------- launch -----------------------------------------------------
extern "C" void kernel_launch(void* const* d_in, const int* in_sizes, int n_in,
                              void* d_out, int out_size) {
    const float* x = (const float*)d_in[0];
    const float* conv1_w = (const float*)d_in[1];
    const float* conv1_b = (const float*)d_in[2];
    const float* prim_w = (const float*)d_in[3];
    const float* prim_b = (const float*)d_in[4];
    const float* route_w = (const float*)d_in[5];
    const float* dec_w1 = (const float*)d_in[6];
    const float* dec_b1 = (const float*)d_in[7];
    const float* dec_w2 = (const float*)d_in[8];
    const float* dec_b2 = (const float*)d_in[9];
    const float* dec_w3 = (const float*)d_in[10];
    const float* dec_b3 = (const float*)d_in[11];
    float* out = (float*)d_out;

    const int SM_ROUTE = 22144 * sizeof(float);   // 88576
    const int SM_DEC = 12496 * sizeof(float);     // 49984
    cudaFuncSetAttribute(k_route, cudaFuncAttributeMaxDynamicSharedMemorySize,
                         SM_ROUTE);
    cudaFuncSetAttribute(k_dec, cudaFuncAttributeMaxDynamicSharedMemorySize,
                         SM_DEC);

    k_wT<<<(256 * 81 * 256) / 256, 256>>>(prim_w);
    k_conv1<<<NB, 256>>>(x, conv1_w, conv1_b);
    k_conv2<<<NB, 256>>>(prim_b);
    k_squash<<<(NB * NROUTE) / 128, 128>>>();
    k_route<<<dim3(NCLS, NB), 256, SM_ROUTE>>>(route_w);
    k_dec<<<NB / 8, 256, SM_DEC>>>(dec_w1, dec_b1, dec_w2, dec_b2, dec_w3,
                                   dec_b3, out);
}

// round 9
// speedup vs baseline: 1.8254x; 1.7123x over previous
#include <cuda_runtime.h>
#include <cuda_bf16.h>
#include <math.h>

#define NB 512
#define NROUTE 1152
#define NCLS 10

// ---------------- scratch ----------------------------------------------------
__device__ float g_h[NB * 256 * 400];          // conv1 out [B,256,20,20]
__device__ __nv_bfloat16 g_wbh[256 * 81 * 256]; // prim_w hi [(ic*81+tap)*256+oc]
__device__ __nv_bfloat16 g_wbl[256 * 81 * 256]; // prim_w lo
__device__ float g_u[NB * NROUTE * 8];         // squashed primary caps
__device__ float g_v[NCLS * NB * 16];          // routed outputs [C,B,16]

// ---------------- ptx helpers ------------------------------------------------
__device__ __forceinline__ unsigned smem_u32(const void* p) {
    unsigned a;
    asm("{ .reg .u64 t; cvta.to.shared.u64 t, %1; cvt.u32.u64 %0, t; }"
        : "=r"(a) : "l"(p));
    return a;
}
__device__ __forceinline__ void ldsm_x4(unsigned* r, unsigned a) {
    asm volatile(
        "ldmatrix.sync.aligned.m8n8.x4.shared.b16 {%0,%1,%2,%3}, [%4];"
        : "=r"(r[0]), "=r"(r[1]), "=r"(r[2]), "=r"(r[3]) : "r"(a));
}
__device__ __forceinline__ void ldsm_x2t(unsigned* r, unsigned a) {
    asm volatile(
        "ldmatrix.sync.aligned.m8n8.x2.trans.shared.b16 {%0,%1}, [%2];"
        : "=r"(r[0]), "=r"(r[1]) : "r"(a));
}
__device__ __forceinline__ void mma_bf16(float* c, const unsigned* a,
                                         const unsigned* b) {
    asm volatile(
        "mma.sync.aligned.m16n8k16.row.col.f32.bf16.bf16.f32 "
        "{%0,%1,%2,%3}, {%4,%5,%6,%7}, {%8,%9}, {%0,%1,%2,%3};"
        : "+f"(c[0]), "+f"(c[1]), "+f"(c[2]), "+f"(c[3])
        : "r"(a[0]), "r"(a[1]), "r"(a[2]), "r"(a[3]), "r"(b[0]), "r"(b[1]));
}

// ---------------- K0: split prim_w into bf16 hi/lo ---------------------------
__global__ void k_wsplit(const float* __restrict__ w) {
    int idx = blockIdx.x * 256 + threadIdx.x;   // 256*81*256 exact
    int oc = idx & 255;
    int rest = idx >> 8;
    int tap = rest % 81;
    int ic = rest / 81;
    float v = w[(oc * 256 + ic) * 81 + tap];
    __nv_bfloat16 h = __float2bfloat16(v);
    g_wbh[idx] = h;
    g_wbl[idx] = __float2bfloat16(v - __bfloat162float(h));
}

// ---------------- K1: conv1 9x9 s1 + relu ------------------------------------
__global__ void __launch_bounds__(256) k_conv1(const float* __restrict__ x,
                                               const float* __restrict__ w,
                                               const float* __restrict__ bias) {
    __shared__ float xs[784];
    int b = blockIdx.x, t = threadIdx.x;
    for (int j = t; j < 784; j += 256) xs[j] = x[b * 784 + j];
    __syncthreads();
    int oc = t;
    const float* wo = w + oc * 81;
    float bv = bias[oc];
    float* ho = g_h + (b * 256 + oc) * 400;
#pragma unroll 1
    for (int orow = 0; orow < 20; orow++) {
        float acc[20];
#pragma unroll
        for (int i = 0; i < 20; i++) acc[i] = 0.f;
#pragma unroll 1
        for (int ky = 0; ky < 9; ky++) {
            const float* xrp = xs + (orow + ky) * 28;
            float xr[28];
#pragma unroll
            for (int i = 0; i < 28; i++) xr[i] = xrp[i];
#pragma unroll
            for (int kx = 0; kx < 9; kx++) {
                float wv = wo[ky * 9 + kx];
#pragma unroll
                for (int ox = 0; ox < 20; ox++)
                    acc[ox] = fmaf(wv, xr[ox + kx], acc[ox]);
            }
        }
#pragma unroll
        for (int ox = 0; ox < 20; ox++) {
            float v = acc[ox] + bv;
            ho[orow * 20 + ox] = v > 0.f ? v : 0.f;
        }
    }
}

// ---------------- K2: tensor-core primary-caps conv + squash -----------------
// smem layout (bytes): hs_hi[0, 76800) rows R=b_l*400+sp, stride 48, 16 ic bf16
//                      hs_lo[76800, 153600)
//                      ws[153600 + buf*16896 + split*8448): 16 rows x 528B
// epilogue reuses [0, 149760) as Cs[144][260] f32
#define HS_LO_OFF 76800
#define WS_OFF 153600
#define WS_BUF 16896
#define WS_SPL 8448
#define SM_CONV2 187392

__device__ __forceinline__ void stage_hs(char* smc, int b0, int ic0, int t) {
#pragma unroll 1
    for (int k = 0; k < 25; k++) {
        int e = t + k * 256;            // 0..6399 float4s
        int f4 = e % 100;
        int ic_l = (e / 100) & 15;
        int b_l = e / 1600;
        float4 v4 = *(const float4*)(g_h + (b0 + b_l) * 102400 +
                                     (ic0 + ic_l) * 400 + f4 * 4);
        int Rb = b_l * 400 + f4 * 4;
        float vv[4] = {v4.x, v4.y, v4.z, v4.w};
#pragma unroll
        for (int j = 0; j < 4; j++) {
            float v = vv[j];
            __nv_bfloat16 h = __float2bfloat16(v);
            __nv_bfloat16 l = __float2bfloat16(v - __bfloat162float(h));
            int off = (Rb + j) * 48 + ic_l * 2;
            *(__nv_bfloat16*)(smc + off) = h;
            *(__nv_bfloat16*)(smc + HS_LO_OFF + off) = l;
        }
    }
}

__device__ __forceinline__ void stage_ws_async(unsigned sbase, int it, int buf,
                                               int t) {
    int chunk = it / 81, tap = it - chunk * 81;
    int row = t >> 4, cg = t & 15;
    long src = ((long)((chunk * 16 + row) * 81 + tap)) * 256 + cg * 16;
    unsigned dst = sbase + WS_OFF + buf * WS_BUF + row * 528 + cg * 32;
    const __nv_bfloat16* ph = g_wbh + src;
    const __nv_bfloat16* pl_ = g_wbl + src;
    asm volatile(
        "cp.async.ca.shared.global [%0], [%1], 16;\n\t"
        "cp.async.ca.shared.global [%2], [%3], 16;\n\t"
        "cp.async.ca.shared.global [%4], [%5], 16;\n\t"
        "cp.async.ca.shared.global [%6], [%7], 16;"
        :: "r"(dst), "l"(ph), "r"(dst + 16), "l"(ph + 8),
           "r"(dst + WS_SPL), "l"(pl_), "r"(dst + WS_SPL + 16), "l"(pl_ + 8));
}

__global__ void __launch_bounds__(256) k_conv2t(const float* __restrict__ bias) {
    extern __shared__ char smc[];
    const unsigned sbase = smem_u32(smc);
    int t = threadIdx.x, lane = t & 31, wid = t >> 5;
    int b0 = blockIdx.x * 4;

    float acc[9][4][4];
#pragma unroll
    for (int s9 = 0; s9 < 9; s9++)
#pragma unroll
        for (int nf = 0; nf < 4; nf++)
#pragma unroll
            for (int i = 0; i < 4; i++) acc[s9][nf][i] = 0.f;

    // per-lane ldmatrix row base offsets (bytes) per m16 slab
    int slabR[9];
    {
        int pl = (lane & 7) + ((lane >> 3) & 1) * 8;
        int badd = ((lane >> 4) & 1) * 16;
#pragma unroll
        for (int s9 = 0; s9 < 9; s9++) {
            int p = s9 * 16 + pl;
            int bl = p / 36, s = p % 36, r = s / 6, ox = s % 6;
            slabR[s9] = (bl * 400 + 40 * r + 2 * ox) * 48 + badd;
        }
    }

    stage_hs(smc, b0, 0, t);
    stage_ws_async(sbase, 0, 0, t);
    asm volatile("cp.async.commit_group;");
    asm volatile("cp.async.wait_group 0;" ::: "memory");
    __syncthreads();

    int buf = 0, ky = 0, kx = 0;
#pragma unroll 1
    for (int it = 0; it < 1296; it++) {
        if (it + 1 < 1296) stage_ws_async(sbase, it + 1, buf ^ 1, t);
        asm volatile("cp.async.commit_group;");

        // B fragments (hi & lo) for this tap, reused across all 9 slabs
        unsigned wsb = sbase + WS_OFF + buf * WS_BUF;
        unsigned brow = wsb + (lane & 15) * 528 + wid * 64;
        unsigned bh[4][2], blf[4][2];
#pragma unroll
        for (int nf = 0; nf < 4; nf++) {
            ldsm_x2t(bh[nf], brow + nf * 16);
            ldsm_x2t(blf[nf], brow + WS_SPL + nf * 16);
        }

        int delta = (20 * ky + kx) * 48;
#pragma unroll
        for (int s9 = 0; s9 < 9; s9++) {
            unsigned ah[4], al[4];
            unsigned aaddr = sbase + slabR[s9] + delta;
            ldsm_x4(ah, aaddr);
            ldsm_x4(al, aaddr + HS_LO_OFF);
#pragma unroll
            for (int nf = 0; nf < 4; nf++) {
                mma_bf16(acc[s9][nf], ah, bh[nf]);
                mma_bf16(acc[s9][nf], ah, blf[nf]);
                mma_bf16(acc[s9][nf], al, bh[nf]);
            }
        }
        asm volatile("cp.async.wait_group 0;" ::: "memory");
        __syncthreads();
        buf ^= 1;
        // advance tap
        if (++kx == 9) {
            kx = 0;
            if (++ky == 9) {
                ky = 0;
                if (it + 1 < 1296) {        // new ic-chunk: restage hs
                    stage_hs(smc, b0, ((it + 1) / 81) * 16, t);
                    __syncthreads();
                }
            }
        }
    }

    // epilogue: bias + store to smem Cs[144][260]
    float* Cs = (float*)smc;
    int grp = lane >> 2, q = lane & 3;
    int ocb = wid * 32 + 2 * q;
    float bset[4][2];
#pragma unroll
    for (int nf = 0; nf < 4; nf++) {
        bset[nf][0] = bias[ocb + nf * 8];
        bset[nf][1] = bias[ocb + nf * 8 + 1];
    }
#pragma unroll
    for (int s9 = 0; s9 < 9; s9++) {
        int p0 = s9 * 16 + grp;
#pragma unroll
        for (int nf = 0; nf < 4; nf++) {
            int oc = ocb + nf * 8;
            Cs[p0 * 260 + oc] = acc[s9][nf][0] + bset[nf][0];
            Cs[p0 * 260 + oc + 1] = acc[s9][nf][1] + bset[nf][1];
            Cs[(p0 + 8) * 260 + oc] = acc[s9][nf][2] + bset[nf][0];
            Cs[(p0 + 8) * 260 + oc + 1] = acc[s9][nf][3] + bset[nf][1];
        }
    }
    __syncthreads();

    // fused capsule gather + squash -> g_u
#pragma unroll 1
    for (int k = 0; k < 18; k++) {
        int cap = t + k * 256;            // 4 batches * 1152 caps
        int b_l = cap / 1152;
        int n = cap - b_l * 1152;
        int c = n / 36, s = n - c * 36;
        const float* row = Cs + (b_l * 36 + s) * 260 + c;
        float tv[8], sn = 0.f;
#pragma unroll
        for (int g = 0; g < 8; g++) {
            tv[g] = row[g * 32];
            sn = fmaf(tv[g], tv[g], sn);
        }
        float sc = sn / ((1.f + sn) * sqrtf(sn));
        float* up = g_u + ((b0 + b_l) * 1152 + n) * 8;
#pragma unroll
        for (int g = 0; g < 8; g++) up[g] = tv[g] * sc;
    }
}

// ---------------- K4: priors + 3-iter dynamic routing (fused) ----------------
__global__ void __launch_bounds__(256) k_route(const float* __restrict__ rw_all) {
    extern __shared__ float sm[];
    float* pri = sm;                    // 1152*17
    float* logits = pri + 19584;
    float* probs = logits + 1152;
    float* red = probs + 1152;
    __shared__ float wb[8];
    __shared__ float sbuf[17];

    int c = blockIdx.x, b = blockIdx.y, t = threadIdx.x;
    int lane = t & 31, wid = t >> 5;
    const float* ub = g_u + b * (NROUTE * 8);
    const float* rw = rw_all + c * (NROUTE * 128);

    for (int j = t; j < 18432; j += 256) {
        int n = j >> 4, o = j & 15;
        const float* up = ub + n * 8;
        const float* rp = rw + n * 128 + o;
        float s = 0.f;
#pragma unroll
        for (int i = 0; i < 8; i++) s = fmaf(up[i], rp[i * 16], s);
        pri[n * 17 + o] = s;
    }
    for (int j = t; j < 1152; j += 256) logits[j] = 0.f;
    __syncthreads();

    int oo = t & 15, sl = t >> 4;

    for (int it = 0; it < 3; it++) {
        float lm = -1e30f;
        for (int n = t; n < 1152; n += 256) lm = fmaxf(lm, logits[n]);
#pragma unroll
        for (int off = 16; off > 0; off >>= 1)
            lm = fmaxf(lm, __shfl_xor_sync(0xffffffffu, lm, off));
        if (lane == 0) wb[wid] = lm;
        __syncthreads();
        float m = wb[0];
#pragma unroll
        for (int k = 1; k < 8; k++) m = fmaxf(m, wb[k]);
        __syncthreads();

        float ls = 0.f;
        for (int n = t; n < 1152; n += 256) {
            float e = __expf(logits[n] - m);
            probs[n] = e;
            ls += e;
        }
#pragma unroll
        for (int off = 16; off > 0; off >>= 1)
            ls += __shfl_xor_sync(0xffffffffu, ls, off);
        if (lane == 0) wb[wid] = ls;
        __syncthreads();
        float Z = 0.f;
#pragma unroll
        for (int k = 0; k < 8; k++) Z += wb[k];
        float inv = 1.f / Z;

        float sp = 0.f;
        for (int n = sl; n < 1152; n += 16)
            sp = fmaf(probs[n], pri[n * 17 + oo], sp);
        red[t] = sp;
        __syncthreads();
        if (t < 16) {
            float s = 0.f;
#pragma unroll
            for (int k = 0; k < 16; k++) s += red[k * 16 + t];
            sbuf[t] = s * inv;
        }
        __syncthreads();
        if (t == 0) {
            float sn = 0.f;
#pragma unroll
            for (int o = 0; o < 16; o++) sn = fmaf(sbuf[o], sbuf[o], sn);
            sbuf[16] = sn / ((1.f + sn) * sqrtf(sn));
        }
        __syncthreads();
        float scale = sbuf[16];

        if (it < 2) {
            for (int n = t; n < 1152; n += 256) {
                const float* pp = pri + n * 17;
                float d = 0.f;
#pragma unroll
                for (int o = 0; o < 16; o++) d = fmaf(pp[o], sbuf[o], d);
                logits[n] += d * scale;
            }
        } else {
            if (t < 16) g_v[(c * NB + b) * 16 + t] = sbuf[t] * scale;
        }
        __syncthreads();
    }
}

// ---------------- K5: classes/argmax/mask + decoder MLP ----------------------
__global__ void __launch_bounds__(256) k_dec(
    const float* __restrict__ w1, const float* __restrict__ b1,
    const float* __restrict__ w2, const float* __restrict__ b2,
    const float* __restrict__ w3, const float* __restrict__ b3,
    float* __restrict__ out) {
    extern __shared__ float sm[];
    float* h1 = sm;
    float* h2 = sm + 4096;
    float* vcap = h2 + 8192;
    float* cl = vcap + 128;
    __shared__ int cls[8];

    int t = threadIdx.x;
    int b0 = blockIdx.x * 8;
    const int RECON_OFF = NB * NCLS;
    const int CLS_OFF = RECON_OFF + NB * 784;

    if (t < 80) {
        int bb = t / 10, c = t - bb * 10;
        const float* vp = g_v + (c * NB + b0 + bb) * 16;
        float sn = 0.f;
#pragma unroll
        for (int o = 0; o < 16; o++) sn = fmaf(vp[o], vp[o], sn);
        float nv = sqrtf(sn);
        cl[bb * 10 + c] = nv;
        out[CLS_OFF + (b0 + bb) * 10 + c] = nv;
    }
    __syncthreads();
    if (t < 8) {
        float m = -1e30f;
        int idx = 0;
        for (int c = 0; c < 10; c++) {
            float v = cl[t * 10 + c];
            if (v > m) { m = v; idx = c; }
        }
        cls[t] = idx;
    }
    __syncthreads();
    if (t < 80) {
        int bb = t / 10, c = t - bb * 10;
        out[(b0 + bb) * 10 + c] = (c == cls[bb]) ? 1.f : 0.f;
    }
    if (t < 128) {
        int bb = t >> 4, o = t & 15;
        vcap[t] = g_v[(cls[bb] * NB + b0 + bb) * 16 + o];
    }
    __syncthreads();

#pragma unroll
    for (int jj = 0; jj < 2; jj++) {
        int j = t + jj * 256;
        float a[8];
        float bv = b1[j];
#pragma unroll
        for (int bb = 0; bb < 8; bb++) a[bb] = bv;
#pragma unroll 1
        for (int bb = 0; bb < 8; bb++) {
            const float* wr = w1 + (cls[bb] * 16) * 512 + j;
#pragma unroll
            for (int o = 0; o < 16; o++)
                a[bb] = fmaf(vcap[bb * 16 + o], wr[o * 512], a[bb]);
        }
#pragma unroll
        for (int bb = 0; bb < 8; bb++)
            h1[bb * 512 + j] = a[bb] > 0.f ? a[bb] : 0.f;
    }
    __syncthreads();

#pragma unroll 1
    for (int jj = 0; jj < 4; jj++) {
        int j = t + jj * 256;
        float a[8];
        float bv = b2[j];
#pragma unroll
        for (int bb = 0; bb < 8; bb++) a[bb] = bv;
#pragma unroll 4
        for (int k = 0; k < 512; k++) {
            float wv = w2[k * 1024 + j];
#pragma unroll
            for (int bb = 0; bb < 8; bb++)
                a[bb] = fmaf(wv, h1[bb * 512 + k], a[bb]);
        }
#pragma unroll
        for (int bb = 0; bb < 8; bb++)
            h2[bb * 1024 + j] = a[bb] > 0.f ? a[bb] : 0.f;
    }
    __syncthreads();

#pragma unroll 1
    for (int j = t; j < 784; j += 256) {
        float a[8];
        float bv = b3[j];
#pragma unroll
        for (int bb = 0; bb < 8; bb++) a[bb] = bv;
#pragma unroll 4
        for (int k = 0; k < 1024; k++) {
            float wv = w3[k * 784 + j];
#pragma unroll
            for (int bb = 0; bb < 8; bb++)
                a[bb] = fmaf(wv, h2[bb * 1024 + k], a[bb]);
        }
#pragma unroll
        for (int bb = 0; bb < 8; bb++)
            out[RECON_OFF + (b0 + bb) * 784 + j] = 1.f / (1.f + expf(-a[bb]));
    }
}

// ---------------- launch -----------------------------------------------------
extern "C" void kernel_launch(void* const* d_in, const int* in_sizes, int n_in,
                              void* d_out, int out_size) {
    const float* x = (const float*)d_in[0];
    const float* conv1_w = (const float*)d_in[1];
    const float* conv1_b = (const float*)d_in[2];
    const float* prim_w = (const float*)d_in[3];
    const float* prim_b = (const float*)d_in[4];
    const float* route_w = (const float*)d_in[5];
    const float* dec_w1 = (const float*)d_in[6];
    const float* dec_b1 = (const float*)d_in[7];
    const float* dec_w2 = (const float*)d_in[8];
    const float* dec_b2 = (const float*)d_in[9];
    const float* dec_w3 = (const float*)d_in[10];
    const float* dec_b3 = (const float*)d_in[11];
    float* out = (float*)d_out;

    const int SM_ROUTE = 22144 * sizeof(float);
    const int SM_DEC = 12496 * sizeof(float);
    cudaFuncSetAttribute(k_conv2t, cudaFuncAttributeMaxDynamicSharedMemorySize,
                         SM_CONV2);
    cudaFuncSetAttribute(k_route, cudaFuncAttributeMaxDynamicSharedMemorySize,
                         SM_ROUTE);
    cudaFuncSetAttribute(k_dec, cudaFuncAttributeMaxDynamicSharedMemorySize,
                         SM_DEC);

    k_wsplit<<<(256 * 81 * 256) / 256, 256>>>(prim_w);
    k_conv1<<<NB, 256>>>(x, conv1_w, conv1_b);
    k_conv2t<<<128, 256, SM_CONV2>>>(prim_b);
    k_route<<<dim3(NCLS, NB), 256, SM_ROUTE>>>(route_w);
    k_dec<<<NB / 8, 256, SM_DEC>>>(dec_w1, dec_b1, dec_w2, dec_b2, dec_w3,
                                   dec_b3, out);
}

// round 11
// speedup vs baseline: 1.9203x; 1.0520x over previous
#include <cuda_runtime.h>
#include <cuda_bf16.h>
#include <math.h>

#define NB 512
#define NROUTE 1152
#define NCLS 10

// ---------------- scratch ----------------------------------------------------
__device__ float g_h[NB * 256 * 400];           // conv1 out [B,256,20,20]
__device__ __nv_bfloat16 g_wbh[256 * 81 * 256]; // prim_w hi [(ic*81+tap)*256+oc]
__device__ __nv_bfloat16 g_wbl[256 * 81 * 256]; // prim_w lo
__device__ float g_u[NB * NROUTE * 8];          // squashed primary caps
__device__ float g_pri[NCLS * NB * NROUTE * 16]; // priors [c][b][n][o]
__device__ float g_v[NCLS * NB * 16];           // routed outputs [C,B,16]

// ---------------- ptx helpers ------------------------------------------------
__device__ __forceinline__ unsigned smem_u32(const void* p) {
    unsigned a;
    asm("{ .reg .u64 t; cvta.to.shared.u64 t, %1; cvt.u32.u64 %0, t; }"
        : "=r"(a) : "l"(p));
    return a;
}
__device__ __forceinline__ void ldsm_x4(unsigned* r, unsigned a) {
    asm volatile(
        "ldmatrix.sync.aligned.m8n8.x4.shared.b16 {%0,%1,%2,%3}, [%4];"
        : "=r"(r[0]), "=r"(r[1]), "=r"(r[2]), "=r"(r[3]) : "r"(a));
}
__device__ __forceinline__ void ldsm_x2t(unsigned* r, unsigned a) {
    asm volatile(
        "ldmatrix.sync.aligned.m8n8.x2.trans.shared.b16 {%0,%1}, [%2];"
        : "=r"(r[0]), "=r"(r[1]) : "r"(a));
}
__device__ __forceinline__ void mma_bf16(float* c, const unsigned* a,
                                         const unsigned* b) {
    asm volatile(
        "mma.sync.aligned.m16n8k16.row.col.f32.bf16.bf16.f32 "
        "{%0,%1,%2,%3}, {%4,%5,%6,%7}, {%8,%9}, {%0,%1,%2,%3};"
        : "+f"(c[0]), "+f"(c[1]), "+f"(c[2]), "+f"(c[3])
        : "r"(a[0]), "r"(a[1]), "r"(a[2]), "r"(a[3]), "r"(b[0]), "r"(b[1]));
}

// ---------------- K0: split prim_w into bf16 hi/lo ---------------------------
__global__ void k_wsplit(const float* __restrict__ w) {
    int idx = blockIdx.x * 256 + threadIdx.x;   // 256*81*256 exact
    int oc = idx & 255;
    int rest = idx >> 8;
    int tap = rest % 81;
    int ic = rest / 81;
    float v = w[(oc * 256 + ic) * 81 + tap];
    __nv_bfloat16 h = __float2bfloat16(v);
    g_wbh[idx] = h;
    g_wbl[idx] = __float2bfloat16(v - __bfloat162float(h));
}

// ---------------- K1: conv1 9x9 s1 + relu ------------------------------------
__global__ void __launch_bounds__(256) k_conv1(const float* __restrict__ x,
                                               const float* __restrict__ w,
                                               const float* __restrict__ bias) {
    __shared__ float xs[784];
    int b = blockIdx.x, t = threadIdx.x;
    for (int j = t; j < 784; j += 256) xs[j] = x[b * 784 + j];
    __syncthreads();
    int oc = t;
    const float* wo = w + oc * 81;
    float bv = bias[oc];
    float* ho = g_h + (b * 256 + oc) * 400;
#pragma unroll 1
    for (int orow = 0; orow < 20; orow++) {
        float acc[20];
#pragma unroll
        for (int i = 0; i < 20; i++) acc[i] = 0.f;
#pragma unroll 1
        for (int ky = 0; ky < 9; ky++) {
            const float* xrp = xs + (orow + ky) * 28;
            float xr[28];
#pragma unroll
            for (int i = 0; i < 28; i++) xr[i] = xrp[i];
#pragma unroll
            for (int kx = 0; kx < 9; kx++) {
                float wv = wo[ky * 9 + kx];
#pragma unroll
                for (int ox = 0; ox < 20; ox++)
                    acc[ox] = fmaf(wv, xr[ox + kx], acc[ox]);
            }
        }
#pragma unroll
        for (int ox = 0; ox < 20; ox++) {
            float v = acc[ox] + bv;
            ho[orow * 20 + ox] = v > 0.f ? v : 0.f;
        }
    }
}

// ---------------- K2: tensor-core primary-caps conv + squash -----------------
// 2 batches per block, 256 blocks -> 110.6KB smem -> 2 blocks/SM.
// smem (bytes): hs_hi[0,38400) rows R=b_l*400+px, stride 48, 16 ic bf16
//               hs_lo[38400,76800)
//               ws[76800 + buf*16896 + split*8448): 16 rows x 528B
// epilogue reuses [0,74880) as Cs[72][260] f32
#define HS_LO_OFF 38400
#define WS_OFF 76800
#define WS_BUF 16896
#define WS_SPL 8448
#define SM_CONV2 110592

__device__ __forceinline__ void stage_hs(char* smc, int b0, int ic0, int t) {
#pragma unroll 1
    for (int k = 0; k < 13; k++) {
        int e = t + k * 256;            // 0..3199 float4s
        if (e < 3200) {
            int f4 = e % 100;
            int ic_l = (e / 100) & 15;
            int b_l = e / 1600;
            float4 v4 = *(const float4*)(g_h + (b0 + b_l) * 102400 +
                                         (ic0 + ic_l) * 400 + f4 * 4);
            int Rb = b_l * 400 + f4 * 4;
            float vv[4] = {v4.x, v4.y, v4.z, v4.w};
#pragma unroll
            for (int j = 0; j < 4; j++) {
                float v = vv[j];
                __nv_bfloat16 h = __float2bfloat16(v);
                __nv_bfloat16 l = __float2bfloat16(v - __bfloat162float(h));
                int off = (Rb + j) * 48 + ic_l * 2;
                *(__nv_bfloat16*)(smc + off) = h;
                *(__nv_bfloat16*)(smc + HS_LO_OFF + off) = l;
            }
        }
    }
}

__device__ __forceinline__ void stage_ws_async(unsigned sbase, int it, int buf,
                                               int t) {
    int chunk = it / 81, tap = it - chunk * 81;
    int row = t >> 4, cg = t & 15;
    long src = ((long)((chunk * 16 + row) * 81 + tap)) * 256 + cg * 16;
    unsigned dst = sbase + WS_OFF + buf * WS_BUF + row * 528 + cg * 32;
    const __nv_bfloat16* ph = g_wbh + src;
    const __nv_bfloat16* pl_ = g_wbl + src;
    asm volatile(
        "cp.async.ca.shared.global [%0], [%1], 16;\n\t"
        "cp.async.ca.shared.global [%2], [%3], 16;\n\t"
        "cp.async.ca.shared.global [%4], [%5], 16;\n\t"
        "cp.async.ca.shared.global [%6], [%7], 16;"
        :: "r"(dst), "l"(ph), "r"(dst + 16), "l"(ph + 8),
           "r"(dst + WS_SPL), "l"(pl_), "r"(dst + WS_SPL + 16), "l"(pl_ + 8));
}

__global__ void __launch_bounds__(256, 2) k_conv2t(const float* __restrict__ bias) {
    extern __shared__ char smc[];
    const unsigned sbase = smem_u32(smc);
    int t = threadIdx.x, lane = t & 31, wid = t >> 5;
    int b0 = blockIdx.x * 2;

    float acc[5][4][4];
#pragma unroll
    for (int s9 = 0; s9 < 5; s9++)
#pragma unroll
        for (int nf = 0; nf < 4; nf++)
#pragma unroll
            for (int i = 0; i < 4; i++) acc[s9][nf][i] = 0.f;

    // per-lane ldmatrix row base offsets per m16 slab (5 slabs, 80 px, 72 valid)
    int slabR[5];
    {
        int pl = (lane & 7) + ((lane >> 3) & 1) * 8;
        int badd = ((lane >> 4) & 1) * 16;
#pragma unroll
        for (int s9 = 0; s9 < 5; s9++) {
            int p = s9 * 16 + pl;
            if (p >= 72) p -= 72;       // padded rows: wrap to valid (discarded)
            int bl = p / 36, s = p % 36, r = s / 6, ox = s % 6;
            slabR[s9] = (bl * 400 + 40 * r + 2 * ox) * 48 + badd;
        }
    }

    stage_hs(smc, b0, 0, t);
    stage_ws_async(sbase, 0, 0, t);
    asm volatile("cp.async.commit_group;");
    asm volatile("cp.async.wait_group 0;" ::: "memory");
    __syncthreads();

    int buf = 0, ky = 0, kx = 0;
#pragma unroll 1
    for (int it = 0; it < 1296; it++) {
        if (it + 1 < 1296) stage_ws_async(sbase, it + 1, buf ^ 1, t);
        asm volatile("cp.async.commit_group;");

        unsigned wsb = sbase + WS_OFF + buf * WS_BUF;
        unsigned brow = wsb + (lane & 15) * 528 + wid * 64;
        unsigned bh[4][2], blf[4][2];
#pragma unroll
        for (int nf = 0; nf < 4; nf++) {
            ldsm_x2t(bh[nf], brow + nf * 16);
            ldsm_x2t(blf[nf], brow + WS_SPL + nf * 16);
        }

        int delta = (20 * ky + kx) * 48;
#pragma unroll
        for (int s9 = 0; s9 < 5; s9++) {
            unsigned ah[4], al[4];
            unsigned aaddr = sbase + slabR[s9] + delta;
            ldsm_x4(ah, aaddr);
            ldsm_x4(al, aaddr + HS_LO_OFF);
#pragma unroll
            for (int nf = 0; nf < 4; nf++) {
                mma_bf16(acc[s9][nf], ah, bh[nf]);
                mma_bf16(acc[s9][nf], ah, blf[nf]);
                mma_bf16(acc[s9][nf], al, bh[nf]);
            }
        }
        asm volatile("cp.async.wait_group 0;" ::: "memory");
        __syncthreads();
        buf ^= 1;
        if (++kx == 9) {
            kx = 0;
            if (++ky == 9) {
                ky = 0;
                if (it + 1 < 1296) {
                    stage_hs(smc, b0, ((it + 1) / 81) * 16, t);
                    __syncthreads();
                }
            }
        }
    }

    // epilogue: bias + store to smem Cs[72][260]
    float* Cs = (float*)smc;
    int grp = lane >> 2, q = lane & 3;
    int ocb = wid * 32 + 2 * q;
    float bset[4][2];
#pragma unroll
    for (int nf = 0; nf < 4; nf++) {
        bset[nf][0] = bias[ocb + nf * 8];
        bset[nf][1] = bias[ocb + nf * 8 + 1];
    }
#pragma unroll
    for (int s9 = 0; s9 < 5; s9++) {
        int p0 = s9 * 16 + grp;
#pragma unroll
        for (int nf = 0; nf < 4; nf++) {
            int oc = ocb + nf * 8;
            Cs[p0 * 260 + oc] = acc[s9][nf][0] + bset[nf][0];
            Cs[p0 * 260 + oc + 1] = acc[s9][nf][1] + bset[nf][1];
            if (s9 < 4) {
                Cs[(p0 + 8) * 260 + oc] = acc[s9][nf][2] + bset[nf][0];
                Cs[(p0 + 8) * 260 + oc + 1] = acc[s9][nf][3] + bset[nf][1];
            }
        }
    }
    __syncthreads();

    // fused capsule gather + squash -> g_u (2 batches * 1152 caps)
#pragma unroll 1
    for (int k = 0; k < 9; k++) {
        int cap = t + k * 256;
        int b_l = cap / 1152;
        int n = cap - b_l * 1152;
        int c = n / 36, s = n - c * 36;
        const float* row = Cs + (b_l * 36 + s) * 260 + c;
        float tv[8], sn = 0.f;
#pragma unroll
        for (int g = 0; g < 8; g++) {
            tv[g] = row[g * 32];
            sn = fmaf(tv[g], tv[g], sn);
        }
        float sc = sn / ((1.f + sn) * sqrtf(sn));
        float* up = g_u + ((b0 + b_l) * 1152 + n) * 8;
#pragma unroll
        for (int g = 0; g < 8; g++) up[g] = tv[g] * sc;
    }
}

// ---------------- K3: priors GEMM -> g_pri -----------------------------------
// grid (144, 10): block = (8 n's, class c). warp w owns n = n0+w.
// lane: o2 = (lane&7)*2, bh = lane>>3 (4 b per iter). route_w read ONCE.
__global__ void __launch_bounds__(256) k_pri(const float* __restrict__ rw_all) {
    __shared__ float ws[1024];
    __shared__ float us[8192];
    int t = threadIdx.x, lane = t & 31, w = t >> 5;
    int c = blockIdx.y, n0 = blockIdx.x * 8;

    {   // stage ws: 8 n x 128 floats
        const float4* rw4 = (const float4*)rw_all;
        int dn = t >> 5, idx4 = t & 31;
        ((float4*)ws)[t] = rw4[c * 36864 + (n0 + dn) * 32 + idx4];
    }
    __syncthreads();

    int o = (lane & 7) * 2, bh = lane >> 3;
    float wr0[8], wr1[8];
#pragma unroll
    for (int i = 0; i < 8; i++) {
        wr0[i] = ws[w * 128 + i * 16 + o];
        wr1[i] = ws[w * 128 + i * 16 + o + 1];
    }

#pragma unroll 1
    for (int ch = 0; ch < 4; ch++) {
        int bchunk = ch * 128;
        __syncthreads();
        const float4* u4 = (const float4*)g_u;
#pragma unroll
        for (int k = 0; k < 8; k++) {
            int j = t + k * 256;        // 2048 float4s: us[bl][64]
            int bl = j >> 4, r4 = j & 15;
            ((float4*)us)[j] = u4[(bchunk + bl) * 2304 + n0 * 2 + r4];
        }
        __syncthreads();
#pragma unroll 2
        for (int kk = 0; kk < 32; kk++) {
            int bl = kk * 4 + bh;
            const float* up = us + bl * 64 + w * 8;
            float4 ua = *(const float4*)up;
            float4 ub = *(const float4*)(up + 4);
            float a0 = ua.x * wr0[0] + ua.y * wr0[1] + ua.z * wr0[2] +
                       ua.w * wr0[3] + ub.x * wr0[4] + ub.y * wr0[5] +
                       ub.z * wr0[6] + ub.w * wr0[7];
            float a1 = ua.x * wr1[0] + ua.y * wr1[1] + ua.z * wr1[2] +
                       ua.w * wr1[3] + ub.x * wr1[4] + ub.y * wr1[5] +
                       ub.z * wr1[6] + ub.w * wr1[7];
            *(float2*)(g_pri + ((c * NB + bchunk + bl) * NROUTE + n0 + w) * 16 +
                       o) = make_float2(a0, a1);
        }
    }
}

// ---------------- K4: 3-iter dynamic routing (priors from g_pri) -------------
__global__ void __launch_bounds__(256) k_route(void) {
    extern __shared__ float sm[];
    float* pri = sm;                    // 1152*17 (17-pad: conflict-free)
    float* logits = pri + 19584;
    float* probs = logits + 1152;
    float* red = probs + 1152;
    __shared__ float wb[8];
    __shared__ float sbuf[17];

    int c = blockIdx.x, b = blockIdx.y, t = threadIdx.x;
    int lane = t & 31, wid = t >> 5;

    // bulk-load priors into smem
    const float4* gp4 = (const float4*)(g_pri + (c * NB + b) * 18432);
#pragma unroll
    for (int k = 0; k < 18; k++) {
        int j = t + k * 256;            // 4608 float4s
        float4 v = gp4[j];
        int n = j >> 2, q = (j & 3) * 4;
        float* pp = pri + n * 17 + q;
        pp[0] = v.x; pp[1] = v.y; pp[2] = v.z; pp[3] = v.w;
    }
    for (int j = t; j < 1152; j += 256) logits[j] = 0.f;
    __syncthreads();

    int oo = t & 15, sl = t >> 4;

    for (int it = 0; it < 3; it++) {
        float inv;
        if (it == 0) {
            inv = 1.f / 1152.f;          // softmax(0) = uniform
        } else {
            float lm = -1e30f;
            for (int n = t; n < 1152; n += 256) lm = fmaxf(lm, logits[n]);
#pragma unroll
            for (int off = 16; off > 0; off >>= 1)
                lm = fmaxf(lm, __shfl_xor_sync(0xffffffffu, lm, off));
            if (lane == 0) wb[wid] = lm;
            __syncthreads();
            float m = wb[0];
#pragma unroll
            for (int k = 1; k < 8; k++) m = fmaxf(m, wb[k]);
            __syncthreads();

            float ls = 0.f;
            for (int n = t; n < 1152; n += 256) {
                float e = __expf(logits[n] - m);
                probs[n] = e;
                ls += e;
            }
#pragma unroll
            for (int off = 16; off > 0; off >>= 1)
                ls += __shfl_xor_sync(0xffffffffu, ls, off);
            if (lane == 0) wb[wid] = ls;
            __syncthreads();
            float Z = 0.f;
#pragma unroll
            for (int k = 0; k < 8; k++) Z += wb[k];
            inv = 1.f / Z;
        }

        float sp = 0.f;
        if (it == 0) {
            for (int n = sl; n < 1152; n += 16) sp += pri[n * 17 + oo];
        } else {
            for (int n = sl; n < 1152; n += 16)
                sp = fmaf(probs[n], pri[n * 17 + oo], sp);
        }
        red[t] = sp;
        __syncthreads();
        if (t < 16) {
            float s = 0.f;
#pragma unroll
            for (int k = 0; k < 16; k++) s += red[k * 16 + t];
            sbuf[t] = s * inv;
        }
        __syncthreads();
        if (t == 0) {
            float sn = 0.f;
#pragma unroll
            for (int o = 0; o < 16; o++) sn = fmaf(sbuf[o], sbuf[o], sn);
            sbuf[16] = sn / ((1.f + sn) * sqrtf(sn));
        }
        __syncthreads();
        float scale = sbuf[16];

        if (it < 2) {
            for (int n = t; n < 1152; n += 256) {
                const float* pp = pri + n * 17;
                float d = 0.f;
#pragma unroll
                for (int o = 0; o < 16; o++) d = fmaf(pp[o], sbuf[o], d);
                logits[n] += d * scale;
            }
        } else {
            if (t < 16) g_v[(c * NB + b) * 16 + t] = sbuf[t] * scale;
        }
        __syncthreads();
    }
}

// ---------------- K5: classes/argmax/mask + decoder MLP ----------------------
__global__ void __launch_bounds__(256) k_dec(
    const float* __restrict__ w1, const float* __restrict__ b1,
    const float* __restrict__ w2, const float* __restrict__ b2,
    const float* __restrict__ w3, const float* __restrict__ b3,
    float* __restrict__ out) {
    extern __shared__ float sm[];
    float* h1 = sm;
    float* h2 = sm + 4096;
    float* vcap = h2 + 8192;
    float* cl = vcap + 128;
    __shared__ int cls[8];

    int t = threadIdx.x;
    int b0 = blockIdx.x * 8;
    const int RECON_OFF = NB * NCLS;
    const int CLS_OFF = RECON_OFF + NB * 784;

    if (t < 80) {
        int bb = t / 10, c = t - bb * 10;
        const float* vp = g_v + (c * NB + b0 + bb) * 16;
        float sn = 0.f;
#pragma unroll
        for (int o = 0; o < 16; o++) sn = fmaf(vp[o], vp[o], sn);
        float nv = sqrtf(sn);
        cl[bb * 10 + c] = nv;
        out[CLS_OFF + (b0 + bb) * 10 + c] = nv;
    }
    __syncthreads();
    if (t < 8) {
        float m = -1e30f;
        int idx = 0;
        for (int c = 0; c < 10; c++) {
            float v = cl[t * 10 + c];
            if (v > m) { m = v; idx = c; }
        }
        cls[t] = idx;
    }
    __syncthreads();
    if (t < 80) {
        int bb = t / 10, c = t - bb * 10;
        out[(b0 + bb) * 10 + c] = (c == cls[bb]) ? 1.f : 0.f;
    }
    if (t < 128) {
        int bb = t >> 4, o = t & 15;
        vcap[t] = g_v[(cls[bb] * NB + b0 + bb) * 16 + o];
    }
    __syncthreads();

#pragma unroll
    for (int jj = 0; jj < 2; jj++) {
        int j = t + jj * 256;
        float a[8];
        float bv = b1[j];
#pragma unroll
        for (int bb = 0; bb < 8; bb++) a[bb] = bv;
#pragma unroll 1
        for (int bb = 0; bb < 8; bb++) {
            const float* wr = w1 + (cls[bb] * 16) * 512 + j;
#pragma unroll
            for (int o = 0; o < 16; o++)
                a[bb] = fmaf(vcap[bb * 16 + o], wr[o * 512], a[bb]);
        }
#pragma unroll
        for (int bb = 0; bb < 8; bb++)
            h1[bb * 512 + j] = a[bb] > 0.f ? a[bb] : 0.f;
    }
    __syncthreads();

#pragma unroll 1
    for (int jj = 0; jj < 4; jj++) {
        int j = t + jj * 256;
        float a[8];
        float bv = b2[j];
#pragma unroll
        for (int bb = 0; bb < 8; bb++) a[bb] = bv;
#pragma unroll 4
        for (int k = 0; k < 512; k++) {
            float wv = w2[k * 1024 + j];
#pragma unroll
            for (int bb = 0; bb < 8; bb++)
                a[bb] = fmaf(wv, h1[bb * 512 + k], a[bb]);
        }
#pragma unroll
        for (int bb = 0; bb < 8; bb++)
            h2[bb * 1024 + j] = a[bb] > 0.f ? a[bb] : 0.f;
    }
    __syncthreads();

#pragma unroll 1
    for (int j = t; j < 784; j += 256) {
        float a[8];
        float bv = b3[j];
#pragma unroll
        for (int bb = 0; bb < 8; bb++) a[bb] = bv;
#pragma unroll 4
        for (int k = 0; k < 1024; k++) {
            float wv = w3[k * 784 + j];
#pragma unroll
            for (int bb = 0; bb < 8; bb++)
                a[bb] = fmaf(wv, h2[bb * 1024 + k], a[bb]);
        }
#pragma unroll
        for (int bb = 0; bb < 8; bb++)
            out[RECON_OFF + (b0 + bb) * 784 + j] = 1.f / (1.f + expf(-a[bb]));
    }
}

// ---------------- launch -----------------------------------------------------
extern "C" void kernel_launch(void* const* d_in, const int* in_sizes, int n_in,
                              void* d_out, int out_size) {
    const float* x = (const float*)d_in[0];
    const float* conv1_w = (const float*)d_in[1];
    const float* conv1_b = (const float*)d_in[2];
    const float* prim_w = (const float*)d_in[3];
    const float* prim_b = (const float*)d_in[4];
    const float* route_w = (const float*)d_in[5];
    const float* dec_w1 = (const float*)d_in[6];
    const float* dec_b1 = (const float*)d_in[7];
    const float* dec_w2 = (const float*)d_in[8];
    const float* dec_b2 = (const float*)d_in[9];
    const float* dec_w3 = (const float*)d_in[10];
    const float* dec_b3 = (const float*)d_in[11];
    float* out = (float*)d_out;

    const int SM_ROUTE = 22144 * sizeof(float);
    const int SM_DEC = 12496 * sizeof(float);
    cudaFuncSetAttribute(k_conv2t, cudaFuncAttributeMaxDynamicSharedMemorySize,
                         SM_CONV2);
    cudaFuncSetAttribute(k_route, cudaFuncAttributeMaxDynamicSharedMemorySize,
                         SM_ROUTE);
    cudaFuncSetAttribute(k_dec, cudaFuncAttributeMaxDynamicSharedMemorySize,
                         SM_DEC);

    k_wsplit<<<(256 * 81 * 256) / 256, 256>>>(prim_w);
    k_conv1<<<NB, 256>>>(x, conv1_w, conv1_b);
    k_conv2t<<<256, 256, SM_CONV2>>>(prim_b);
    k_pri<<<dim3(144, 10), 256>>>(route_w);
    k_route<<<dim3(NCLS, NB), 256, SM_ROUTE>>>();
    k_dec<<<NB / 8, 256, SM_DEC>>>(dec_w1, dec_b1, dec_w2, dec_b2, dec_w3,
                                   dec_b3, out);
}

// round 13
// speedup vs baseline: 1.9994x; 1.0412x over previous
#include <cuda_runtime.h>
#include <cuda_bf16.h>
#include <math.h>

#define NB 512
#define NROUTE 1152
#define NCLS 10

// ---------------- scratch ----------------------------------------------------
__device__ float g_h[NB * 256 * 400];           // conv1 out [B,256,20,20]
__device__ __nv_bfloat16 g_wbh[256 * 81 * 256]; // prim_w hi [(ic*81+tap)*256+oc]
__device__ __nv_bfloat16 g_wbl[256 * 81 * 256]; // prim_w lo
__device__ float g_u[NB * NROUTE * 8];          // squashed primary caps
__device__ float g_pri[NCLS * NB * NROUTE * 16]; // priors [c][b][n][o]
__device__ float g_v[NCLS * NB * 16];           // routed outputs [C,B,16]

// ---------------- ptx helpers ------------------------------------------------
__device__ __forceinline__ unsigned smem_u32(const void* p) {
    unsigned a;
    asm("{ .reg .u64 t; cvta.to.shared.u64 t, %1; cvt.u32.u64 %0, t; }"
        : "=r"(a) : "l"(p));
    return a;
}
__device__ __forceinline__ void ldsm_x4(unsigned* r, unsigned a) {
    asm volatile(
        "ldmatrix.sync.aligned.m8n8.x4.shared.b16 {%0,%1,%2,%3}, [%4];"
        : "=r"(r[0]), "=r"(r[1]), "=r"(r[2]), "=r"(r[3]) : "r"(a));
}
__device__ __forceinline__ void ldsm_x2t(unsigned* r, unsigned a) {
    asm volatile(
        "ldmatrix.sync.aligned.m8n8.x2.trans.shared.b16 {%0,%1}, [%2];"
        : "=r"(r[0]), "=r"(r[1]) : "r"(a));
}
__device__ __forceinline__ void mma_bf16(float* c, const unsigned* a,
                                         const unsigned* b) {
    asm volatile(
        "mma.sync.aligned.m16n8k16.row.col.f32.bf16.bf16.f32 "
        "{%0,%1,%2,%3}, {%4,%5,%6,%7}, {%8,%9}, {%0,%1,%2,%3};"
        : "+f"(c[0]), "+f"(c[1]), "+f"(c[2]), "+f"(c[3])
        : "r"(a[0]), "r"(a[1]), "r"(a[2]), "r"(a[3]), "r"(b[0]), "r"(b[1]));
}

// ---------------- K0: split prim_w into bf16 hi/lo ---------------------------
__global__ void k_wsplit(const float* __restrict__ w) {
    int idx = blockIdx.x * 256 + threadIdx.x;   // 256*81*256 exact
    int oc = idx & 255;
    int rest = idx >> 8;
    int tap = rest % 81;
    int ic = rest / 81;
    float v = w[(oc * 256 + ic) * 81 + tap];
    __nv_bfloat16 h = __float2bfloat16(v);
    g_wbh[idx] = h;
    g_wbl[idx] = __float2bfloat16(v - __bfloat162float(h));
}

// ---------------- K1: conv1 9x9 s1 + relu ------------------------------------
__global__ void __launch_bounds__(256) k_conv1(const float* __restrict__ x,
                                               const float* __restrict__ w,
                                               const float* __restrict__ bias) {
    __shared__ float xs[784];
    int b = blockIdx.x, t = threadIdx.x;
    for (int j = t; j < 784; j += 256) xs[j] = x[b * 784 + j];
    __syncthreads();
    int oc = t;
    const float* wo = w + oc * 81;
    float bv = bias[oc];
    float* ho = g_h + (b * 256 + oc) * 400;
#pragma unroll 1
    for (int orow = 0; orow < 20; orow++) {
        float acc[20];
#pragma unroll
        for (int i = 0; i < 20; i++) acc[i] = 0.f;
#pragma unroll 1
        for (int ky = 0; ky < 9; ky++) {
            const float* xrp = xs + (orow + ky) * 28;
            float xr[28];
#pragma unroll
            for (int i = 0; i < 28; i++) xr[i] = xrp[i];
#pragma unroll
            for (int kx = 0; kx < 9; kx++) {
                float wv = wo[ky * 9 + kx];
#pragma unroll
                for (int ox = 0; ox < 20; ox++)
                    acc[ox] = fmaf(wv, xr[ox + kx], acc[ox]);
            }
        }
#pragma unroll
        for (int ox = 0; ox < 20; ox++) {
            float v = acc[ox] + bv;
            ho[orow * 20 + ox] = v > 0.f ? v : 0.f;
        }
    }
}

// ---------------- K2: tensor-core primary-caps conv + squash -----------------
// 4 batches per block, 128 blocks. 9 exact m16 slabs, all 256 oc.
// smem (bytes): hs_hi[0,76800) rows R=b_l*400+px, stride 48, 16 ic bf16
//               hs_lo[76800,153600)
//               ws[153600 + buf*16896 + split*8448): 16 rows x 528B
// epilogue reuses [0,149760) as Cs[144][260] f32
#define HS_LO_OFF 76800
#define WS_OFF 153600
#define WS_BUF 16896
#define WS_SPL 8448
#define SM_CONV2 187392

__device__ __forceinline__ void stage_hs(char* smc, int b0, int ic0, int t) {
#pragma unroll 1
    for (int k = 0; k < 25; k++) {
        int e = t + k * 256;            // 0..6399 float4s
        int f4 = e % 100;
        int ic_l = (e / 100) & 15;
        int b_l = e / 1600;
        float4 v4 = *(const float4*)(g_h + (b0 + b_l) * 102400 +
                                     (ic0 + ic_l) * 400 + f4 * 4);
        int Rb = b_l * 400 + f4 * 4;
        float vv[4] = {v4.x, v4.y, v4.z, v4.w};
#pragma unroll
        for (int j = 0; j < 4; j++) {
            float v = vv[j];
            __nv_bfloat16 h = __float2bfloat16(v);
            __nv_bfloat16 l = __float2bfloat16(v - __bfloat162float(h));
            int off = (Rb + j) * 48 + ic_l * 2;
            *(__nv_bfloat16*)(smc + off) = h;
            *(__nv_bfloat16*)(smc + HS_LO_OFF + off) = l;
        }
    }
}

__device__ __forceinline__ void stage_ws_async(unsigned sbase, int it, int buf,
                                               int t) {
    int chunk = it / 81, tap = it - chunk * 81;
    int row = t >> 4, cg = t & 15;
    long src = ((long)((chunk * 16 + row) * 81 + tap)) * 256 + cg * 16;
    unsigned dst = sbase + WS_OFF + buf * WS_BUF + row * 528 + cg * 32;
    const __nv_bfloat16* ph = g_wbh + src;
    const __nv_bfloat16* pl_ = g_wbl + src;
    asm volatile(
        "cp.async.ca.shared.global [%0], [%1], 16;\n\t"
        "cp.async.ca.shared.global [%2], [%3], 16;\n\t"
        "cp.async.ca.shared.global [%4], [%5], 16;\n\t"
        "cp.async.ca.shared.global [%6], [%7], 16;"
        :: "r"(dst), "l"(ph), "r"(dst + 16), "l"(ph + 8),
           "r"(dst + WS_SPL), "l"(pl_), "r"(dst + WS_SPL + 16), "l"(pl_ + 8));
}

__global__ void __launch_bounds__(256) k_conv2t(const float* __restrict__ bias) {
    extern __shared__ char smc[];
    const unsigned sbase = smem_u32(smc);
    int t = threadIdx.x, lane = t & 31, wid = t >> 5;
    int b0 = blockIdx.x * 4;

    float acc[9][4][4];
#pragma unroll
    for (int s9 = 0; s9 < 9; s9++)
#pragma unroll
        for (int nf = 0; nf < 4; nf++)
#pragma unroll
            for (int i = 0; i < 4; i++) acc[s9][nf][i] = 0.f;

    // per-lane ldmatrix row base offsets (bytes) per m16 slab
    int slabR[9];
    {
        int pl = (lane & 7) + ((lane >> 3) & 1) * 8;
        int badd = ((lane >> 4) & 1) * 16;
#pragma unroll
        for (int s9 = 0; s9 < 9; s9++) {
            int p = s9 * 16 + pl;
            int bl = p / 36, s = p % 36, r = s / 6, ox = s % 6;
            slabR[s9] = (bl * 400 + 40 * r + 2 * ox) * 48 + badd;
        }
    }

    stage_hs(smc, b0, 0, t);
    stage_ws_async(sbase, 0, 0, t);
    asm volatile("cp.async.commit_group;");
    asm volatile("cp.async.wait_group 0;" ::: "memory");
    __syncthreads();

    int buf = 0, ky = 0, kx = 0;
#pragma unroll 1
    for (int it = 0; it < 1296; it++) {
        if (it + 1 < 1296) stage_ws_async(sbase, it + 1, buf ^ 1, t);
        asm volatile("cp.async.commit_group;");

        // B fragments (hi & lo) for this tap, reused across all 9 slabs
        unsigned wsb = sbase + WS_OFF + buf * WS_BUF;
        unsigned brow = wsb + (lane & 15) * 528 + wid * 64;
        unsigned bh[4][2], blf[4][2];
#pragma unroll
        for (int nf = 0; nf < 4; nf++) {
            ldsm_x2t(bh[nf], brow + nf * 16);
            ldsm_x2t(blf[nf], brow + WS_SPL + nf * 16);
        }

        int delta = (20 * ky + kx) * 48;
        // slab-triples: load 3 slabs' A frags, then 36 MMAs term-major so
        // same-accumulator reuse distance is 12 MMAs (no RAW stalls)
#pragma unroll
        for (int t3 = 0; t3 < 3; t3++) {
            unsigned ah[3][4], al[3][4];
#pragma unroll
            for (int sl = 0; sl < 3; sl++) {
                unsigned aaddr = sbase + slabR[t3 * 3 + sl] + delta;
                ldsm_x4(ah[sl], aaddr);
                ldsm_x4(al[sl], aaddr + HS_LO_OFF);
            }
#pragma unroll
            for (int sl = 0; sl < 3; sl++)
#pragma unroll
                for (int nf = 0; nf < 4; nf++)
                    mma_bf16(acc[t3 * 3 + sl][nf], ah[sl], bh[nf]);
#pragma unroll
            for (int sl = 0; sl < 3; sl++)
#pragma unroll
                for (int nf = 0; nf < 4; nf++)
                    mma_bf16(acc[t3 * 3 + sl][nf], ah[sl], blf[nf]);
#pragma unroll
            for (int sl = 0; sl < 3; sl++)
#pragma unroll
                for (int nf = 0; nf < 4; nf++)
                    mma_bf16(acc[t3 * 3 + sl][nf], al[sl], bh[nf]);
        }
        asm volatile("cp.async.wait_group 0;" ::: "memory");
        __syncthreads();
        buf ^= 1;
        if (++kx == 9) {
            kx = 0;
            if (++ky == 9) {
                ky = 0;
                if (it + 1 < 1296) {
                    stage_hs(smc, b0, ((it + 1) / 81) * 16, t);
                    __syncthreads();
                }
            }
        }
    }

    // epilogue: bias + store to smem Cs[144][260]
    float* Cs = (float*)smc;
    int grp = lane >> 2, q = lane & 3;
    int ocb = wid * 32 + 2 * q;
    float bset[4][2];
#pragma unroll
    for (int nf = 0; nf < 4; nf++) {
        bset[nf][0] = bias[ocb + nf * 8];
        bset[nf][1] = bias[ocb + nf * 8 + 1];
    }
#pragma unroll
    for (int s9 = 0; s9 < 9; s9++) {
        int p0 = s9 * 16 + grp;
#pragma unroll
        for (int nf = 0; nf < 4; nf++) {
            int oc = ocb + nf * 8;
            Cs[p0 * 260 + oc] = acc[s9][nf][0] + bset[nf][0];
            Cs[p0 * 260 + oc + 1] = acc[s9][nf][1] + bset[nf][1];
            Cs[(p0 + 8) * 260 + oc] = acc[s9][nf][2] + bset[nf][0];
            Cs[(p0 + 8) * 260 + oc + 1] = acc[s9][nf][3] + bset[nf][1];
        }
    }
    __syncthreads();

    // fused capsule gather + squash -> g_u (4 batches * 1152 caps)
#pragma unroll 1
    for (int k = 0; k < 18; k++) {
        int cap = t + k * 256;
        int b_l = cap / 1152;
        int n = cap - b_l * 1152;
        int c = n / 36, s = n - c * 36;
        const float* row = Cs + (b_l * 36 + s) * 260 + c;
        float tv[8], sn = 0.f;
#pragma unroll
        for (int g = 0; g < 8; g++) {
            tv[g] = row[g * 32];
            sn = fmaf(tv[g], tv[g], sn);
        }
        float sc = sn / ((1.f + sn) * sqrtf(sn));
        float* up = g_u + ((b0 + b_l) * 1152 + n) * 8;
#pragma unroll
        for (int g = 0; g < 8; g++) up[g] = tv[g] * sc;
    }
}

// ---------------- K3: priors GEMM -> g_pri -----------------------------------
__global__ void __launch_bounds__(256) k_pri(const float* __restrict__ rw_all) {
    __shared__ float ws[1024];
    __shared__ float us[8192];
    int t = threadIdx.x, lane = t & 31, w = t >> 5;
    int c = blockIdx.y, n0 = blockIdx.x * 8;

    {
        const float4* rw4 = (const float4*)rw_all;
        int dn = t >> 5, idx4 = t & 31;
        ((float4*)ws)[t] = rw4[c * 36864 + (n0 + dn) * 32 + idx4];
    }
    __syncthreads();

    int o = (lane & 7) * 2, bh = lane >> 3;
    float wr0[8], wr1[8];
#pragma unroll
    for (int i = 0; i < 8; i++) {
        wr0[i] = ws[w * 128 + i * 16 + o];
        wr1[i] = ws[w * 128 + i * 16 + o + 1];
    }

#pragma unroll 1
    for (int ch = 0; ch < 4; ch++) {
        int bchunk = ch * 128;
        __syncthreads();
        const float4* u4 = (const float4*)g_u;
#pragma unroll
        for (int k = 0; k < 8; k++) {
            int j = t + k * 256;
            int bl = j >> 4, r4 = j & 15;
            ((float4*)us)[j] = u4[(bchunk + bl) * 2304 + n0 * 2 + r4];
        }
        __syncthreads();
#pragma unroll 2
        for (int kk = 0; kk < 32; kk++) {
            int bl = kk * 4 + bh;
            const float* up = us + bl * 64 + w * 8;
            float4 ua = *(const float4*)up;
            float4 ub = *(const float4*)(up + 4);
            float a0 = ua.x * wr0[0] + ua.y * wr0[1] + ua.z * wr0[2] +
                       ua.w * wr0[3] + ub.x * wr0[4] + ub.y * wr0[5] +
                       ub.z * wr0[6] + ub.w * wr0[7];
            float a1 = ua.x * wr1[0] + ua.y * wr1[1] + ua.z * wr1[2] +
                       ua.w * wr1[3] + ub.x * wr1[4] + ub.y * wr1[5] +
                       ub.z * wr1[6] + ub.w * wr1[7];
            *(float2*)(g_pri + ((c * NB + bchunk + bl) * NROUTE + n0 + w) * 16 +
                       o) = make_float2(a0, a1);
        }
    }
}

// ---------------- K4: 3-iter dynamic routing ---------------------------------
__global__ void __launch_bounds__(256) k_route(void) {
    extern __shared__ float sm[];
    float* pri = sm;
    float* logits = pri + 19584;
    float* probs = logits + 1152;
    float* red = probs + 1152;
    __shared__ float wb[8];
    __shared__ float sbuf[17];

    int c = blockIdx.x, b = blockIdx.y, t = threadIdx.x;
    int lane = t & 31, wid = t >> 5;

    const float4* gp4 = (const float4*)(g_pri + (c * NB + b) * 18432);
#pragma unroll
    for (int k = 0; k < 18; k++) {
        int j = t + k * 256;
        float4 v = gp4[j];
        int n = j >> 2, q = (j & 3) * 4;
        float* pp = pri + n * 17 + q;
        pp[0] = v.x; pp[1] = v.y; pp[2] = v.z; pp[3] = v.w;
    }
    for (int j = t; j < 1152; j += 256) logits[j] = 0.f;
    __syncthreads();

    int oo = t & 15, sl = t >> 4;

    for (int it = 0; it < 3; it++) {
        float inv;
        if (it == 0) {
            inv = 1.f / 1152.f;
        } else {
            float lm = -1e30f;
            for (int n = t; n < 1152; n += 256) lm = fmaxf(lm, logits[n]);
#pragma unroll
            for (int off = 16; off > 0; off >>= 1)
                lm = fmaxf(lm, __shfl_xor_sync(0xffffffffu, lm, off));
            if (lane == 0) wb[wid] = lm;
            __syncthreads();
            float m = wb[0];
#pragma unroll
            for (int k = 1; k < 8; k++) m = fmaxf(m, wb[k]);
            __syncthreads();

            float ls = 0.f;
            for (int n = t; n < 1152; n += 256) {
                float e = __expf(logits[n] - m);
                probs[n] = e;
                ls += e;
            }
#pragma unroll
            for (int off = 16; off > 0; off >>= 1)
                ls += __shfl_xor_sync(0xffffffffu, ls, off);
            if (lane == 0) wb[wid] = ls;
            __syncthreads();
            float Z = 0.f;
#pragma unroll
            for (int k = 0; k < 8; k++) Z += wb[k];
            inv = 1.f / Z;
        }

        float sp = 0.f;
        if (it == 0) {
            for (int n = sl; n < 1152; n += 16) sp += pri[n * 17 + oo];
        } else {
            for (int n = sl; n < 1152; n += 16)
                sp = fmaf(probs[n], pri[n * 17 + oo], sp);
        }
        red[t] = sp;
        __syncthreads();
        if (t < 16) {
            float s = 0.f;
#pragma unroll
            for (int k = 0; k < 16; k++) s += red[k * 16 + t];
            sbuf[t] = s * inv;
        }
        __syncthreads();
        if (t == 0) {
            float sn = 0.f;
#pragma unroll
            for (int o = 0; o < 16; o++) sn = fmaf(sbuf[o], sbuf[o], sn);
            sbuf[16] = sn / ((1.f + sn) * sqrtf(sn));
        }
        __syncthreads();
        float scale = sbuf[16];

        if (it < 2) {
            for (int n = t; n < 1152; n += 256) {
                const float* pp = pri + n * 17;
                float d = 0.f;
#pragma unroll
                for (int o = 0; o < 16; o++) d = fmaf(pp[o], sbuf[o], d);
                logits[n] += d * scale;
            }
        } else {
            if (t < 16) g_v[(c * NB + b) * 16 + t] = sbuf[t] * scale;
        }
        __syncthreads();
    }
}

// ---------------- K5: classes/argmax/mask + decoder MLP ----------------------
__global__ void __launch_bounds__(256) k_dec(
    const float* __restrict__ w1, const float* __restrict__ b1,
    const float* __restrict__ w2, const float* __restrict__ b2,
    const float* __restrict__ w3, const float* __restrict__ b3,
    float* __restrict__ out) {
    extern __shared__ float sm[];
    float* h1 = sm;
    float* h2 = sm + 4096;
    float* vcap = h2 + 8192;
    float* cl = vcap + 128;
    __shared__ int cls[8];

    int t = threadIdx.x;
    int b0 = blockIdx.x * 8;
    const int RECON_OFF = NB * NCLS;
    const int CLS_OFF = RECON_OFF + NB * 784;

    if (t < 80) {
        int bb = t / 10, c = t - bb * 10;
        const float* vp = g_v + (c * NB + b0 + bb) * 16;
        float sn = 0.f;
#pragma unroll
        for (int o = 0; o < 16; o++) sn = fmaf(vp[o], vp[o], sn);
        float nv = sqrtf(sn);
        cl[bb * 10 + c] = nv;
        out[CLS_OFF + (b0 + bb) * 10 + c] = nv;
    }
    __syncthreads();
    if (t < 8) {
        float m = -1e30f;
        int idx = 0;
        for (int c = 0; c < 10; c++) {
            float v = cl[t * 10 + c];
            if (v > m) { m = v; idx = c; }
        }
        cls[t] = idx;
    }
    __syncthreads();
    if (t < 80) {
        int bb = t / 10, c = t - bb * 10;
        out[(b0 + bb) * 10 + c] = (c == cls[bb]) ? 1.f : 0.f;
    }
    if (t < 128) {
        int bb = t >> 4, o = t & 15;
        vcap[t] = g_v[(cls[bb] * NB + b0 + bb) * 16 + o];
    }
    __syncthreads();

#pragma unroll
    for (int jj = 0; jj < 2; jj++) {
        int j = t + jj * 256;
        float a[8];
        float bv = b1[j];
#pragma unroll
        for (int bb = 0; bb < 8; bb++) a[bb] = bv;
#pragma unroll 1
        for (int bb = 0; bb < 8; bb++) {
            const float* wr = w1 + (cls[bb] * 16) * 512 + j;
#pragma unroll
            for (int o = 0; o < 16; o++)
                a[bb] = fmaf(vcap[bb * 16 + o], wr[o * 512], a[bb]);
        }
#pragma unroll
        for (int bb = 0; bb < 8; bb++)
            h1[bb * 512 + j] = a[bb] > 0.f ? a[bb] : 0.f;
    }
    __syncthreads();

#pragma unroll 1
    for (int jj = 0; jj < 4; jj++) {
        int j = t + jj * 256;
        float a[8];
        float bv = b2[j];
#pragma unroll
        for (int bb = 0; bb < 8; bb++) a[bb] = bv;
#pragma unroll 4
        for (int k = 0; k < 512; k++) {
            float wv = w2[k * 1024 + j];
#pragma unroll
            for (int bb = 0; bb < 8; bb++)
                a[bb] = fmaf(wv, h1[bb * 512 + k], a[bb]);
        }
#pragma unroll
        for (int bb = 0; bb < 8; bb++)
            h2[bb * 1024 + j] = a[bb] > 0.f ? a[bb] : 0.f;
    }
    __syncthreads();

#pragma unroll 1
    for (int j = t; j < 784; j += 256) {
        float a[8];
        float bv = b3[j];
#pragma unroll
        for (int bb = 0; bb < 8; bb++) a[bb] = bv;
#pragma unroll 4
        for (int k = 0; k < 1024; k++) {
            float wv = w3[k * 784 + j];
#pragma unroll
            for (int bb = 0; bb < 8; bb++)
                a[bb] = fmaf(wv, h2[bb * 1024 + k], a[bb]);
        }
#pragma unroll
        for (int bb = 0; bb < 8; bb++)
            out[RECON_OFF + (b0 + bb) * 784 + j] = 1.f / (1.f + expf(-a[bb]));
    }
}

// ---------------- launch -----------------------------------------------------
extern "C" void kernel_launch(void* const* d_in, const int* in_sizes, int n_in,
                              void* d_out, int out_size) {
    const float* x = (const float*)d_in[0];
    const float* conv1_w = (const float*)d_in[1];
    const float* conv1_b = (const float*)d_in[2];
    const float* prim_w = (const float*)d_in[3];
    const float* prim_b = (const float*)d_in[4];
    const float* route_w = (const float*)d_in[5];
    const float* dec_w1 = (const float*)d_in[6];
    const float* dec_b1 = (const float*)d_in[7];
    const float* dec_w2 = (const float*)d_in[8];
    const float* dec_b2 = (const float*)d_in[9];
    const float* dec_w3 = (const float*)d_in[10];
    const float* dec_b3 = (const float*)d_in[11];
    float* out = (float*)d_out;

    const int SM_ROUTE = 22144 * sizeof(float);
    const int SM_DEC = 12496 * sizeof(float);
    cudaFuncSetAttribute(k_conv2t, cudaFuncAttributeMaxDynamicSharedMemorySize,
                         SM_CONV2);
    cudaFuncSetAttribute(k_route, cudaFuncAttributeMaxDynamicSharedMemorySize,
                         SM_ROUTE);
    cudaFuncSetAttribute(k_dec, cudaFuncAttributeMaxDynamicSharedMemorySize,
                         SM_DEC);

    k_wsplit<<<(256 * 81 * 256) / 256, 256>>>(prim_w);
    k_conv1<<<NB, 256>>>(x, conv1_w, conv1_b);
    k_conv2t<<<128, 256, SM_CONV2>>>(prim_b);
    k_pri<<<dim3(144, 10), 256>>>(route_w);
    k_route<<<dim3(NCLS, NB), 256, SM_ROUTE>>>();
    k_dec<<<NB / 8, 256, SM_DEC>>>(dec_w1, dec_b1, dec_w2, dec_b2, dec_w3,
                                   dec_b3, out);
}

// round 15
// speedup vs baseline: 2.1142x; 1.0574x over previous
#include <cuda_runtime.h>
#include <cuda_fp16.h>
#include <math.h>

#define NB 512
#define NROUTE 1152
#define NCLS 10

// ---------------- scratch ----------------------------------------------------
__device__ float g_h[NB * 256 * 400];          // conv1 out [B,256,20,20]
__device__ __half g_wbh[256 * 81 * 256];       // prim_w hi  [(ic*81+tap)*256+oc]
__device__ __half g_wbl[256 * 81 * 256];       // prim_w lo (exact fp16 residual)
__device__ float g_u[NB * NROUTE * 8];         // squashed primary caps
__device__ float g_pri[NCLS * NB * NROUTE * 16]; // priors [c][b][n][o]
__device__ float g_v[NCLS * NB * 16];          // routed outputs [C,B,16]

// ---------------- ptx helpers ------------------------------------------------
__device__ __forceinline__ unsigned smem_u32(const void* p) {
    unsigned a;
    asm("{ .reg .u64 t; cvta.to.shared.u64 t, %1; cvt.u32.u64 %0, t; }"
        : "=r"(a) : "l"(p));
    return a;
}
__device__ __forceinline__ void ldsm_x4(unsigned* r, unsigned a) {
    asm volatile(
        "ldmatrix.sync.aligned.m8n8.x4.shared.b16 {%0,%1,%2,%3}, [%4];"
        : "=r"(r[0]), "=r"(r[1]), "=r"(r[2]), "=r"(r[3]) : "r"(a));
}
__device__ __forceinline__ void ldsm_x2t(unsigned* r, unsigned a) {
    asm volatile(
        "ldmatrix.sync.aligned.m8n8.x2.trans.shared.b16 {%0,%1}, [%2];"
        : "=r"(r[0]), "=r"(r[1]) : "r"(a));
}
__device__ __forceinline__ void mma_f16(float* c, const unsigned* a,
                                        const unsigned* b) {
    asm volatile(
        "mma.sync.aligned.m16n8k16.row.col.f32.f16.f16.f32 "
        "{%0,%1,%2,%3}, {%4,%5,%6,%7}, {%8,%9}, {%0,%1,%2,%3};"
        : "+f"(c[0]), "+f"(c[1]), "+f"(c[2]), "+f"(c[3])
        : "r"(a[0]), "r"(a[1]), "r"(a[2]), "r"(a[3]), "r"(b[0]), "r"(b[1]));
}

// ---------------- K0: split prim_w into fp16 hi + exact residual lo ---------
__global__ void k_wsplit(const float* __restrict__ w) {
    int idx = blockIdx.x * 256 + threadIdx.x;   // 256*81*256 exact
    int oc = idx & 255;
    int rest = idx >> 8;
    int tap = rest % 81;
    int ic = rest / 81;
    float v = w[(oc * 256 + ic) * 81 + tap];
    __half h = __float2half_rn(v);
    g_wbh[idx] = h;
    g_wbl[idx] = __float2half_rn(v - __half2float(h));
}

// ---------------- K1: conv1 9x9 s1 + relu ------------------------------------
__global__ void __launch_bounds__(256) k_conv1(const float* __restrict__ x,
                                               const float* __restrict__ w,
                                               const float* __restrict__ bias) {
    __shared__ float xs[784];
    int b = blockIdx.x, t = threadIdx.x;
    for (int j = t; j < 784; j += 256) xs[j] = x[b * 784 + j];
    __syncthreads();
    int oc = t;
    const float* wo = w + oc * 81;
    float bv = bias[oc];
    float* ho = g_h + (b * 256 + oc) * 400;
#pragma unroll 1
    for (int orow = 0; orow < 20; orow++) {
        float acc[20];
#pragma unroll
        for (int i = 0; i < 20; i++) acc[i] = 0.f;
#pragma unroll 1
        for (int ky = 0; ky < 9; ky++) {
            const float* xrp = xs + (orow + ky) * 28;
            float xr[28];
#pragma unroll
            for (int i = 0; i < 28; i++) xr[i] = xrp[i];
#pragma unroll
            for (int kx = 0; kx < 9; kx++) {
                float wv = wo[ky * 9 + kx];
#pragma unroll
                for (int ox = 0; ox < 20; ox++)
                    acc[ox] = fmaf(wv, xr[ox + kx], acc[ox]);
            }
        }
#pragma unroll
        for (int ox = 0; ox < 20; ox++) {
            float v = acc[ox] + bv;
            ho[orow * 20 + ox] = v > 0.f ? v : 0.f;
        }
    }
}

// ---------------- K2: tensor-core primary-caps conv + squash -----------------
// 4 batches per block, 128 blocks. 9 exact m16 slabs, all 256 oc.
// C = fp16(A) x (Bh + Bl), B-split exact -> only A-rounding error (~2^-11).
// smem (bytes): hs[0,76800) rows R=b_l*400+px, stride 48, 16 ic fp16
//               ws[76800 + buf*16896 + split*8448): 16 rows x 528B
// epilogue reuses [0,149760) as Cs[144][260] f32
#define WS_OFF 76800
#define WS_BUF 16896
#define WS_SPL 8448
#define SM_CONV2 149760

__device__ __forceinline__ void stage_hs(char* smc, int b0, int ic0, int t) {
#pragma unroll 1
    for (int k = 0; k < 25; k++) {
        int e = t + k * 256;            // 0..6399 float4s
        int f4 = e % 100;
        int ic_l = (e / 100) & 15;
        int b_l = e / 1600;
        float4 v4 = *(const float4*)(g_h + (b0 + b_l) * 102400 +
                                     (ic0 + ic_l) * 400 + f4 * 4);
        int Rb = b_l * 400 + f4 * 4;
        float vv[4] = {v4.x, v4.y, v4.z, v4.w};
#pragma unroll
        for (int j = 0; j < 4; j++) {
            int off = (Rb + j) * 48 + ic_l * 2;
            *(__half*)(smc + off) = __float2half_rn(vv[j]);
        }
    }
}

__device__ __forceinline__ void stage_ws_async(unsigned sbase, int it, int buf,
                                               int t) {
    int chunk = it / 81, tap = it - chunk * 81;
    int row = t >> 4, cg = t & 15;
    long src = ((long)((chunk * 16 + row) * 81 + tap)) * 256 + cg * 16;
    unsigned dst = sbase + WS_OFF + buf * WS_BUF + row * 528 + cg * 32;
    const __half* ph = g_wbh + src;
    const __half* pl_ = g_wbl + src;
    asm volatile(
        "cp.async.ca.shared.global [%0], [%1], 16;\n\t"
        "cp.async.ca.shared.global [%2], [%3], 16;\n\t"
        "cp.async.ca.shared.global [%4], [%5], 16;\n\t"
        "cp.async.ca.shared.global [%6], [%7], 16;"
        :: "r"(dst), "l"(ph), "r"(dst + 16), "l"(ph + 8),
           "r"(dst + WS_SPL), "l"(pl_), "r"(dst + WS_SPL + 16), "l"(pl_ + 8));
}

__global__ void __launch_bounds__(256) k_conv2t(const float* __restrict__ bias) {
    extern __shared__ char smc[];
    const unsigned sbase = smem_u32(smc);
    int t = threadIdx.x, lane = t & 31, wid = t >> 5;
    int b0 = blockIdx.x * 4;

    float acc[9][4][4];
#pragma unroll
    for (int s9 = 0; s9 < 9; s9++)
#pragma unroll
        for (int nf = 0; nf < 4; nf++)
#pragma unroll
            for (int i = 0; i < 4; i++) acc[s9][nf][i] = 0.f;

    // per-lane ldmatrix row base offsets (bytes) per m16 slab
    int slabR[9];
    {
        int pl = (lane & 7) + ((lane >> 3) & 1) * 8;
        int badd = ((lane >> 4) & 1) * 16;
#pragma unroll
        for (int s9 = 0; s9 < 9; s9++) {
            int p = s9 * 16 + pl;
            int bl = p / 36, s = p % 36, r = s / 6, ox = s % 6;
            slabR[s9] = (bl * 400 + 40 * r + 2 * ox) * 48 + badd;
        }
    }

    stage_hs(smc, b0, 0, t);
    stage_ws_async(sbase, 0, 0, t);
    asm volatile("cp.async.commit_group;");
    asm volatile("cp.async.wait_group 0;" ::: "memory");
    __syncthreads();

    int buf = 0, ky = 0, kx = 0;
#pragma unroll 1
    for (int it = 0; it < 1296; it++) {
        if (it + 1 < 1296) stage_ws_async(sbase, it + 1, buf ^ 1, t);
        asm volatile("cp.async.commit_group;");

        // B fragments (hi & lo) for this tap, reused across all 9 slabs
        unsigned wsb = sbase + WS_OFF + buf * WS_BUF;
        unsigned brow = wsb + (lane & 15) * 528 + wid * 64;
        unsigned bh[4][2], blf[4][2];
#pragma unroll
        for (int nf = 0; nf < 4; nf++) {
            ldsm_x2t(bh[nf], brow + nf * 16);
            ldsm_x2t(blf[nf], brow + WS_SPL + nf * 16);
        }

        int delta = (20 * ky + kx) * 48;
        // slab-triples, term-major: same-acc reuse distance 12 MMAs
#pragma unroll
        for (int t3 = 0; t3 < 3; t3++) {
            unsigned ah[3][4];
#pragma unroll
            for (int sl = 0; sl < 3; sl++)
                ldsm_x4(ah[sl], sbase + slabR[t3 * 3 + sl] + delta);
#pragma unroll
            for (int sl = 0; sl < 3; sl++)
#pragma unroll
                for (int nf = 0; nf < 4; nf++)
                    mma_f16(acc[t3 * 3 + sl][nf], ah[sl], bh[nf]);
#pragma unroll
            for (int sl = 0; sl < 3; sl++)
#pragma unroll
                for (int nf = 0; nf < 4; nf++)
                    mma_f16(acc[t3 * 3 + sl][nf], ah[sl], blf[nf]);
        }
        asm volatile("cp.async.wait_group 0;" ::: "memory");
        __syncthreads();
        buf ^= 1;
        if (++kx == 9) {
            kx = 0;
            if (++ky == 9) {
                ky = 0;
                if (it + 1 < 1296) {
                    stage_hs(smc, b0, ((it + 1) / 81) * 16, t);
                    __syncthreads();
                }
            }
        }
    }

    // epilogue: bias + store to smem Cs[144][260]
    float* Cs = (float*)smc;
    int grp = lane >> 2, q = lane & 3;
    int ocb = wid * 32 + 2 * q;
    float bset[4][2];
#pragma unroll
    for (int nf = 0; nf < 4; nf++) {
        bset[nf][0] = bias[ocb + nf * 8];
        bset[nf][1] = bias[ocb + nf * 8 + 1];
    }
#pragma unroll
    for (int s9 = 0; s9 < 9; s9++) {
        int p0 = s9 * 16 + grp;
#pragma unroll
        for (int nf = 0; nf < 4; nf++) {
            int oc = ocb + nf * 8;
            Cs[p0 * 260 + oc] = acc[s9][nf][0] + bset[nf][0];
            Cs[p0 * 260 + oc + 1] = acc[s9][nf][1] + bset[nf][1];
            Cs[(p0 + 8) * 260 + oc] = acc[s9][nf][2] + bset[nf][0];
            Cs[(p0 + 8) * 260 + oc + 1] = acc[s9][nf][3] + bset[nf][1];
        }
    }
    __syncthreads();

    // fused capsule gather + squash -> g_u (4 batches * 1152 caps)
#pragma unroll 1
    for (int k = 0; k < 18; k++) {
        int cap = t + k * 256;
        int b_l = cap / 1152;
        int n = cap - b_l * 1152;
        int c = n / 36, s = n - c * 36;
        const float* row = Cs + (b_l * 36 + s) * 260 + c;
        float tv[8], sn = 0.f;
#pragma unroll
        for (int g = 0; g < 8; g++) {
            tv[g] = row[g * 32];
            sn = fmaf(tv[g], tv[g], sn);
        }
        float sc = sn / ((1.f + sn) * sqrtf(sn));
        float* up = g_u + ((b0 + b_l) * 1152 + n) * 8;
#pragma unroll
        for (int g = 0; g < 8; g++) up[g] = tv[g] * sc;
    }
}

// ---------------- K3: priors GEMM -> g_pri -----------------------------------
__global__ void __launch_bounds__(256) k_pri(const float* __restrict__ rw_all) {
    __shared__ float ws[1024];
    __shared__ float us[8192];
    int t = threadIdx.x, lane = t & 31, w = t >> 5;
    int c = blockIdx.y, n0 = blockIdx.x * 8;

    {
        const float4* rw4 = (const float4*)rw_all;
        int dn = t >> 5, idx4 = t & 31;
        ((float4*)ws)[t] = rw4[c * 36864 + (n0 + dn) * 32 + idx4];
    }
    __syncthreads();

    int o = (lane & 7) * 2, bh = lane >> 3;
    float wr0[8], wr1[8];
#pragma unroll
    for (int i = 0; i < 8; i++) {
        wr0[i] = ws[w * 128 + i * 16 + o];
        wr1[i] = ws[w * 128 + i * 16 + o + 1];
    }

#pragma unroll 1
    for (int ch = 0; ch < 4; ch++) {
        int bchunk = ch * 128;
        __syncthreads();
        const float4* u4 = (const float4*)g_u;
#pragma unroll
        for (int k = 0; k < 8; k++) {
            int j = t + k * 256;
            int bl = j >> 4, r4 = j & 15;
            ((float4*)us)[j] = u4[(bchunk + bl) * 2304 + n0 * 2 + r4];
        }
        __syncthreads();
#pragma unroll 2
        for (int kk = 0; kk < 32; kk++) {
            int bl = kk * 4 + bh;
            const float* up = us + bl * 64 + w * 8;
            float4 ua = *(const float4*)up;
            float4 ub = *(const float4*)(up + 4);
            float a0 = ua.x * wr0[0] + ua.y * wr0[1] + ua.z * wr0[2] +
                       ua.w * wr0[3] + ub.x * wr0[4] + ub.y * wr0[5] +
                       ub.z * wr0[6] + ub.w * wr0[7];
            float a1 = ua.x * wr1[0] + ua.y * wr1[1] + ua.z * wr1[2] +
                       ua.w * wr1[3] + ub.x * wr1[4] + ub.y * wr1[5] +
                       ub.z * wr1[6] + ub.w * wr1[7];
            *(float2*)(g_pri + ((c * NB + bchunk + bl) * NROUTE + n0 + w) * 16 +
                       o) = make_float2(a0, a1);
        }
    }
}

// ---------------- K4: 3-iter dynamic routing ---------------------------------
__global__ void __launch_bounds__(256) k_route(void) {
    extern __shared__ float sm[];
    float* pri = sm;
    float* logits = pri + 19584;
    float* probs = logits + 1152;
    float* red = probs + 1152;
    __shared__ float wb[8];
    __shared__ float sbuf[17];

    int c = blockIdx.x, b = blockIdx.y, t = threadIdx.x;
    int lane = t & 31, wid = t >> 5;

    const float4* gp4 = (const float4*)(g_pri + (c * NB + b) * 18432);
#pragma unroll
    for (int k = 0; k < 18; k++) {
        int j = t + k * 256;
        float4 v = gp4[j];
        int n = j >> 2, q = (j & 3) * 4;
        float* pp = pri + n * 17 + q;
        pp[0] = v.x; pp[1] = v.y; pp[2] = v.z; pp[3] = v.w;
    }
    for (int j = t; j < 1152; j += 256) logits[j] = 0.f;
    __syncthreads();

    int oo = t & 15, sl = t >> 4;

    for (int it = 0; it < 3; it++) {
        float inv;
        if (it == 0) {
            inv = 1.f / 1152.f;
        } else {
            float lm = -1e30f;
            for (int n = t; n < 1152; n += 256) lm = fmaxf(lm, logits[n]);
#pragma unroll
            for (int off = 16; off > 0; off >>= 1)
                lm = fmaxf(lm, __shfl_xor_sync(0xffffffffu, lm, off));
            if (lane == 0) wb[wid] = lm;
            __syncthreads();
            float m = wb[0];
#pragma unroll
            for (int k = 1; k < 8; k++) m = fmaxf(m, wb[k]);
            __syncthreads();

            float ls = 0.f;
            for (int n = t; n < 1152; n += 256) {
                float e = __expf(logits[n] - m);
                probs[n] = e;
                ls += e;
            }
#pragma unroll
            for (int off = 16; off > 0; off >>= 1)
                ls += __shfl_xor_sync(0xffffffffu, ls, off);
            if (lane == 0) wb[wid] = ls;
            __syncthreads();
            float Z = 0.f;
#pragma unroll
            for (int k = 0; k < 8; k++) Z += wb[k];
            inv = 1.f / Z;
        }

        float sp = 0.f;
        if (it == 0) {
            for (int n = sl; n < 1152; n += 16) sp += pri[n * 17 + oo];
        } else {
            for (int n = sl; n < 1152; n += 16)
                sp = fmaf(probs[n], pri[n * 17 + oo], sp);
        }
        red[t] = sp;
        __syncthreads();
        if (t < 16) {
            float s = 0.f;
#pragma unroll
            for (int k = 0; k < 16; k++) s += red[k * 16 + t];
            sbuf[t] = s * inv;
        }
        __syncthreads();
        if (t == 0) {
            float sn = 0.f;
#pragma unroll
            for (int o = 0; o < 16; o++) sn = fmaf(sbuf[o], sbuf[o], sn);
            sbuf[16] = sn / ((1.f + sn) * sqrtf(sn));
        }
        __syncthreads();
        float scale = sbuf[16];

        if (it < 2) {
            for (int n = t; n < 1152; n += 256) {
                const float* pp = pri + n * 17;
                float d = 0.f;
#pragma unroll
                for (int o = 0; o < 16; o++) d = fmaf(pp[o], sbuf[o], d);
                logits[n] += d * scale;
            }
        } else {
            if (t < 16) g_v[(c * NB + b) * 16 + t] = sbuf[t] * scale;
        }
        __syncthreads();
    }
}

// ---------------- K5: classes/argmax/mask + decoder MLP ----------------------
__global__ void __launch_bounds__(256) k_dec(
    const float* __restrict__ w1, const float* __restrict__ b1,
    const float* __restrict__ w2, const float* __restrict__ b2,
    const float* __restrict__ w3, const float* __restrict__ b3,
    float* __restrict__ out) {
    extern __shared__ float sm[];
    float* h1 = sm;
    float* h2 = sm + 4096;
    float* vcap = h2 + 8192;
    float* cl = vcap + 128;
    __shared__ int cls[8];

    int t = threadIdx.x;
    int b0 = blockIdx.x * 8;
    const int RECON_OFF = NB * NCLS;
    const int CLS_OFF = RECON_OFF + NB * 784;

    if (t < 80) {
        int bb = t / 10, c = t - bb * 10;
        const float* vp = g_v + (c * NB + b0 + bb) * 16;
        float sn = 0.f;
#pragma unroll
        for (int o = 0; o < 16; o++) sn = fmaf(vp[o], vp[o], sn);
        float nv = sqrtf(sn);
        cl[bb * 10 + c] = nv;
        out[CLS_OFF + (b0 + bb) * 10 + c] = nv;
    }
    __syncthreads();
    if (t < 8) {
        float m = -1e30f;
        int idx = 0;
        for (int c = 0; c < 10; c++) {
            float v = cl[t * 10 + c];
            if (v > m) { m = v; idx = c; }
        }
        cls[t] = idx;
    }
    __syncthreads();
    if (t < 80) {
        int bb = t / 10, c = t - bb * 10;
        out[(b0 + bb) * 10 + c] = (c == cls[bb]) ? 1.f : 0.f;
    }
    if (t < 128) {
        int bb = t >> 4, o = t & 15;
        vcap[t] = g_v[(cls[bb] * NB + b0 + bb) * 16 + o];
    }
    __syncthreads();

#pragma unroll
    for (int jj = 0; jj < 2; jj++) {
        int j = t + jj * 256;
        float a[8];
        float bv = b1[j];
#pragma unroll
        for (int bb = 0; bb < 8; bb++) a[bb] = bv;
#pragma unroll 1
        for (int bb = 0; bb < 8; bb++) {
            const float* wr = w1 + (cls[bb] * 16) * 512 + j;
#pragma unroll
            for (int o = 0; o < 16; o++)
                a[bb] = fmaf(vcap[bb * 16 + o], wr[o * 512], a[bb]);
        }
#pragma unroll
        for (int bb = 0; bb < 8; bb++)
            h1[bb * 512 + j] = a[bb] > 0.f ? a[bb] : 0.f;
    }
    __syncthreads();

#pragma unroll 1
    for (int jj = 0; jj < 4; jj++) {
        int j = t + jj * 256;
        float a[8];
        float bv = b2[j];
#pragma unroll
        for (int bb = 0; bb < 8; bb++) a[bb] = bv;
#pragma unroll 4
        for (int k = 0; k < 512; k++) {
            float wv = w2[k * 1024 + j];
#pragma unroll
            for (int bb = 0; bb < 8; bb++)
                a[bb] = fmaf(wv, h1[bb * 512 + k], a[bb]);
        }
#pragma unroll
        for (int bb = 0; bb < 8; bb++)
            h2[bb * 1024 + j] = a[bb] > 0.f ? a[bb] : 0.f;
    }
    __syncthreads();

#pragma unroll 1
    for (int j = t; j < 784; j += 256) {
        float a[8];
        float bv = b3[j];
#pragma unroll
        for (int bb = 0; bb < 8; bb++) a[bb] = bv;
#pragma unroll 4
        for (int k = 0; k < 1024; k++) {
            float wv = w3[k * 784 + j];
#pragma unroll
            for (int bb = 0; bb < 8; bb++)
                a[bb] = fmaf(wv, h2[bb * 1024 + k], a[bb]);
        }
#pragma unroll
        for (int bb = 0; bb < 8; bb++)
            out[RECON_OFF + (b0 + bb) * 784 + j] = 1.f / (1.f + expf(-a[bb]));
    }
}

// ---------------- launch -----------------------------------------------------
extern "C" void kernel_launch(void* const* d_in, const int* in_sizes, int n_in,
                              void* d_out, int out_size) {
    const float* x = (const float*)d_in[0];
    const float* conv1_w = (const float*)d_in[1];
    const float* conv1_b = (const float*)d_in[2];
    const float* prim_w = (const float*)d_in[3];
    const float* prim_b = (const float*)d_in[4];
    const float* route_w = (const float*)d_in[5];
    const float* dec_w1 = (const float*)d_in[6];
    const float* dec_b1 = (const float*)d_in[7];
    const float* dec_w2 = (const float*)d_in[8];
    const float* dec_b2 = (const float*)d_in[9];
    const float* dec_w3 = (const float*)d_in[10];
    const float* dec_b3 = (const float*)d_in[11];
    float* out = (float*)d_out;

    const int SM_ROUTE = 22144 * sizeof(float);
    const int SM_DEC = 12496 * sizeof(float);
    cudaFuncSetAttribute(k_conv2t, cudaFuncAttributeMaxDynamicSharedMemorySize,
                         SM_CONV2);
    cudaFuncSetAttribute(k_route, cudaFuncAttributeMaxDynamicSharedMemorySize,
                         SM_ROUTE);
    cudaFuncSetAttribute(k_dec, cudaFuncAttributeMaxDynamicSharedMemorySize,
                         SM_DEC);

    k_wsplit<<<(256 * 81 * 256) / 256, 256>>>(prim_w);
    k_conv1<<<NB, 256>>>(x, conv1_w, conv1_b);
    k_conv2t<<<128, 256, SM_CONV2>>>(prim_b);
    k_pri<<<dim3(144, 10), 256>>>(route_w);
    k_route<<<dim3(NCLS, NB), 256, SM_ROUTE>>>();
    k_dec<<<NB / 8, 256, SM_DEC>>>(dec_w1, dec_b1, dec_w2, dec_b2, dec_w3,
                                   dec_b3, out);
}

// round 16
// speedup vs baseline: 2.5620x; 1.2118x over previous
#include <cuda_runtime.h>
#include <cuda_fp16.h>
#include <math.h>

#define NB 512
#define NROUTE 1152
#define NCLS 10

// ---------------- scratch ----------------------------------------------------
__device__ float g_h[NB * 256 * 400];          // conv1 out [B,256,20,20]
__device__ unsigned g_wfrag[16 * 81 * 4096];   // frag-ordered weights (20.7MB)
__device__ float g_u[NB * NROUTE * 8];         // squashed primary caps
__device__ float g_pri[NCLS * NB * NROUTE * 16]; // priors [c][b][n][o]
__device__ float g_v[NCLS * NB * 16];          // routed outputs [C,B,16]

// ---------------- ptx helpers ------------------------------------------------
__device__ __forceinline__ unsigned smem_u32(const void* p) {
    unsigned a;
    asm("{ .reg .u64 t; cvta.to.shared.u64 t, %1; cvt.u32.u64 %0, t; }"
        : "=r"(a) : "l"(p));
    return a;
}
__device__ __forceinline__ void ldsm_x4(unsigned* r, unsigned a) {
    asm volatile(
        "ldmatrix.sync.aligned.m8n8.x4.shared.b16 {%0,%1,%2,%3}, [%4];"
        : "=r"(r[0]), "=r"(r[1]), "=r"(r[2]), "=r"(r[3]) : "r"(a));
}
__device__ __forceinline__ void mma_f16(float* c, const unsigned* a,
                                        const unsigned* b) {
    asm volatile(
        "mma.sync.aligned.m16n8k16.row.col.f32.f16.f16.f32 "
        "{%0,%1,%2,%3}, {%4,%5,%6,%7}, {%8,%9}, {%0,%1,%2,%3};"
        : "+f"(c[0]), "+f"(c[1]), "+f"(c[2]), "+f"(c[3])
        : "r"(a[0]), "r"(a[1]), "r"(a[2]), "r"(a[3]), "r"(b[0]), "r"(b[1]));
}

// ---------------- K0: weights -> fragment-ordered gmem (fp16 hi + exact lo) --
// layout per (ct = chunk*81+tap): 4 stripes x 256 uint4.
// stripe 0/1 = hi split (nf 0-1 / nf 2-3), stripe 2/3 = lo split.
// uint4 for thread t = {nf_a.b0, nf_a.b1, nf_b.b0, nf_b.b1}
// b0 = half2{W[k0],W[k0+1]}, b1 = half2{W[k0+8],W[k0+9]},
// k0 = (lane&3)*2, oc = wid*32 + nf*8 + lane/4, ic = chunk*16 + k.
__global__ void k_wsplit(const float* __restrict__ w) {
    int u = blockIdx.x * 256 + threadIdx.x;     // 16*81*256 = 331776 exact
    int t_ = u & 255;
    int ct = u >> 8;                             // 0..1295
    int chunk = ct / 81, tap = ct - chunk * 81;
    int lane = t_ & 31, wid5 = t_ >> 5;
    int k0 = (lane & 3) * 2, ncol = lane >> 2;
    uint4* outp = (uint4*)g_wfrag + (ct << 10) + t_;
#pragma unroll
    for (int np = 0; np < 2; np++) {
        unsigned hw[4], lw[4];
#pragma unroll
        for (int w2 = 0; w2 < 2; w2++) {
            int oc = wid5 * 32 + (np * 2 + w2) * 8 + ncol;
#pragma unroll
            for (int rr = 0; rr < 2; rr++) {
                int ic = chunk * 16 + k0 + rr * 8;
                float v0 = w[(oc * 256 + ic) * 81 + tap];
                float v1 = w[(oc * 256 + ic + 1) * 81 + tap];
                __half h0 = __float2half_rn(v0), h1 = __float2half_rn(v1);
                __half l0 = __float2half_rn(v0 - __half2float(h0));
                __half l1 = __float2half_rn(v1 - __half2float(h1));
                hw[w2 * 2 + rr] = (unsigned)__half_as_ushort(h0) |
                                  ((unsigned)__half_as_ushort(h1) << 16);
                lw[w2 * 2 + rr] = (unsigned)__half_as_ushort(l0) |
                                  ((unsigned)__half_as_ushort(l1) << 16);
            }
        }
        outp[np * 256] = make_uint4(hw[0], hw[1], hw[2], hw[3]);
        outp[(2 + np) * 256] = make_uint4(lw[0], lw[1], lw[2], lw[3]);
    }
}

// ---------------- K1: conv1 9x9 s1 + relu ------------------------------------
__global__ void __launch_bounds__(256) k_conv1(const float* __restrict__ x,
                                               const float* __restrict__ w,
                                               const float* __restrict__ bias) {
    __shared__ float xs[784];
    int b = blockIdx.x, t = threadIdx.x;
    for (int j = t; j < 784; j += 256) xs[j] = x[b * 784 + j];
    __syncthreads();
    int oc = t;
    const float* wo = w + oc * 81;
    float bv = bias[oc];
    float* ho = g_h + (b * 256 + oc) * 400;
#pragma unroll 1
    for (int orow = 0; orow < 20; orow++) {
        float acc[20];
#pragma unroll
        for (int i = 0; i < 20; i++) acc[i] = 0.f;
#pragma unroll 1
        for (int ky = 0; ky < 9; ky++) {
            const float* xrp = xs + (orow + ky) * 28;
            float xr[28];
#pragma unroll
            for (int i = 0; i < 28; i++) xr[i] = xrp[i];
#pragma unroll
            for (int kx = 0; kx < 9; kx++) {
                float wv = wo[ky * 9 + kx];
#pragma unroll
                for (int ox = 0; ox < 20; ox++)
                    acc[ox] = fmaf(wv, xr[ox + kx], acc[ox]);
            }
        }
#pragma unroll
        for (int ox = 0; ox < 20; ox++) {
            float v = acc[ox] + bv;
            ho[orow * 20 + ox] = v > 0.f ? v : 0.f;
        }
    }
}

// ---------------- K2: tensor-core primary-caps conv + squash -----------------
// 4 batches per block, 128 blocks. 9 exact m16 slabs, all 256 oc.
// B fragments loaded DIRECTLY from frag-ordered gmem (L2-resident) — no ws
// smem, no cp.async, no per-tap barriers.
// smem: hs[0,76800) rows R=b_l*400+px, stride 48, 16 ic fp16.
// epilogue reuses [0,149760) as Cs[144][260] f32
#define SM_CONV2 149760

__device__ __forceinline__ void stage_hs(char* smc, int b0, int ic0, int t) {
#pragma unroll 1
    for (int k = 0; k < 25; k++) {
        int e = t + k * 256;            // 0..6399 float4s
        int f4 = e % 100;
        int ic_l = (e / 100) & 15;
        int b_l = e / 1600;
        float4 v4 = *(const float4*)(g_h + (b0 + b_l) * 102400 +
                                     (ic0 + ic_l) * 400 + f4 * 4);
        int Rb = b_l * 400 + f4 * 4;
        float vv[4] = {v4.x, v4.y, v4.z, v4.w};
#pragma unroll
        for (int j = 0; j < 4; j++) {
            int off = (Rb + j) * 48 + ic_l * 2;
            *(__half*)(smc + off) = __float2half_rn(vv[j]);
        }
    }
}

__global__ void __launch_bounds__(256) k_conv2t(const float* __restrict__ bias) {
    extern __shared__ char smc[];
    const unsigned sbase = smem_u32(smc);
    int t = threadIdx.x, lane = t & 31, wid = t >> 5;
    int b0 = blockIdx.x * 4;

    float acc[9][4][4];
#pragma unroll
    for (int s9 = 0; s9 < 9; s9++)
#pragma unroll
        for (int nf = 0; nf < 4; nf++)
#pragma unroll
            for (int i = 0; i < 4; i++) acc[s9][nf][i] = 0.f;

    // per-lane ldmatrix row base offsets (bytes) per m16 slab
    int slabR[9];
    {
        int pl = (lane & 7) + ((lane >> 3) & 1) * 8;
        int badd = ((lane >> 4) & 1) * 16;
#pragma unroll
        for (int s9 = 0; s9 < 9; s9++) {
            int p = s9 * 16 + pl;
            int bl = p / 36, s = p % 36, r = s / 6, ox = s % 6;
            slabR[s9] = (bl * 400 + 40 * r + 2 * ox) * 48 + badd;
        }
    }

#pragma unroll 1
    for (int chunk = 0; chunk < 16; chunk++) {
        __syncthreads();
        stage_hs(smc, b0, chunk * 16, t);
        __syncthreads();
        const uint4* wfc = (const uint4*)g_wfrag + ((chunk * 81) << 10) + t;
#pragma unroll 3
        for (int tap = 0; tap < 81; tap++) {
            uint4 f0 = __ldg(wfc);
            uint4 f1 = __ldg(wfc + 256);
            uint4 f2 = __ldg(wfc + 512);
            uint4 f3 = __ldg(wfc + 768);
            wfc += 1024;
            unsigned bh[4][2] = {{f0.x, f0.y}, {f0.z, f0.w},
                                 {f1.x, f1.y}, {f1.z, f1.w}};
            unsigned bl2[4][2] = {{f2.x, f2.y}, {f2.z, f2.w},
                                  {f3.x, f3.y}, {f3.z, f3.w}};
            int ky = tap / 9, kx = tap - ky * 9;
            int delta = (20 * ky + kx) * 48;
            // slab-triples, term-major: same-acc reuse distance 12 MMAs
#pragma unroll
            for (int t3 = 0; t3 < 3; t3++) {
                unsigned ah[3][4];
#pragma unroll
                for (int sl = 0; sl < 3; sl++)
                    ldsm_x4(ah[sl], sbase + slabR[t3 * 3 + sl] + delta);
#pragma unroll
                for (int sl = 0; sl < 3; sl++)
#pragma unroll
                    for (int nf = 0; nf < 4; nf++)
                        mma_f16(acc[t3 * 3 + sl][nf], ah[sl], bh[nf]);
#pragma unroll
                for (int sl = 0; sl < 3; sl++)
#pragma unroll
                    for (int nf = 0; nf < 4; nf++)
                        mma_f16(acc[t3 * 3 + sl][nf], ah[sl], bl2[nf]);
            }
        }
    }

    // epilogue: bias + store to smem Cs[144][260]
    __syncthreads();
    float* Cs = (float*)smc;
    int grp = lane >> 2, q = lane & 3;
    int ocb = wid * 32 + 2 * q;
    float bset[4][2];
#pragma unroll
    for (int nf = 0; nf < 4; nf++) {
        bset[nf][0] = bias[ocb + nf * 8];
        bset[nf][1] = bias[ocb + nf * 8 + 1];
    }
#pragma unroll
    for (int s9 = 0; s9 < 9; s9++) {
        int p0 = s9 * 16 + grp;
#pragma unroll
        for (int nf = 0; nf < 4; nf++) {
            int oc = ocb + nf * 8;
            Cs[p0 * 260 + oc] = acc[s9][nf][0] + bset[nf][0];
            Cs[p0 * 260 + oc + 1] = acc[s9][nf][1] + bset[nf][1];
            Cs[(p0 + 8) * 260 + oc] = acc[s9][nf][2] + bset[nf][0];
            Cs[(p0 + 8) * 260 + oc + 1] = acc[s9][nf][3] + bset[nf][1];
        }
    }
    __syncthreads();

    // fused capsule gather + squash -> g_u (4 batches * 1152 caps)
#pragma unroll 1
    for (int k = 0; k < 18; k++) {
        int cap = t + k * 256;
        int b_l = cap / 1152;
        int n = cap - b_l * 1152;
        int c = n / 36, s = n - c * 36;
        const float* row = Cs + (b_l * 36 + s) * 260 + c;
        float tv[8], sn = 0.f;
#pragma unroll
        for (int g = 0; g < 8; g++) {
            tv[g] = row[g * 32];
            sn = fmaf(tv[g], tv[g], sn);
        }
        float sc = sn / ((1.f + sn) * sqrtf(sn));
        float* up = g_u + ((b0 + b_l) * 1152 + n) * 8;
#pragma unroll
        for (int g = 0; g < 8; g++) up[g] = tv[g] * sc;
    }
}

// ---------------- K3: priors GEMM -> g_pri -----------------------------------
__global__ void __launch_bounds__(256) k_pri(const float* __restrict__ rw_all) {
    __shared__ float ws[1024];
    __shared__ float us[8192];
    int t = threadIdx.x, lane = t & 31, w = t >> 5;
    int c = blockIdx.y, n0 = blockIdx.x * 8;

    {
        const float4* rw4 = (const float4*)rw_all;
        int dn = t >> 5, idx4 = t & 31;
        ((float4*)ws)[t] = rw4[c * 36864 + (n0 + dn) * 32 + idx4];
    }
    __syncthreads();

    int o = (lane & 7) * 2, bh = lane >> 3;
    float wr0[8], wr1[8];
#pragma unroll
    for (int i = 0; i < 8; i++) {
        wr0[i] = ws[w * 128 + i * 16 + o];
        wr1[i] = ws[w * 128 + i * 16 + o + 1];
    }

#pragma unroll 1
    for (int ch = 0; ch < 4; ch++) {
        int bchunk = ch * 128;
        __syncthreads();
        const float4* u4 = (const float4*)g_u;
#pragma unroll
        for (int k = 0; k < 8; k++) {
            int j = t + k * 256;
            int bl = j >> 4, r4 = j & 15;
            ((float4*)us)[j] = u4[(bchunk + bl) * 2304 + n0 * 2 + r4];
        }
        __syncthreads();
#pragma unroll 2
        for (int kk = 0; kk < 32; kk++) {
            int bl = kk * 4 + bh;
            const float* up = us + bl * 64 + w * 8;
            float4 ua = *(const float4*)up;
            float4 ub = *(const float4*)(up + 4);
            float a0 = ua.x * wr0[0] + ua.y * wr0[1] + ua.z * wr0[2] +
                       ua.w * wr0[3] + ub.x * wr0[4] + ub.y * wr0[5] +
                       ub.z * wr0[6] + ub.w * wr0[7];
            float a1 = ua.x * wr1[0] + ua.y * wr1[1] + ua.z * wr1[2] +
                       ua.w * wr1[3] + ub.x * wr1[4] + ub.y * wr1[5] +
                       ub.z * wr1[6] + ub.w * wr1[7];
            *(float2*)(g_pri + ((c * NB + bchunk + bl) * NROUTE + n0 + w) * 16 +
                       o) = make_float2(a0, a1);
        }
    }
}

// ---------------- K4: 3-iter dynamic routing ---------------------------------
__global__ void __launch_bounds__(256) k_route(void) {
    extern __shared__ float sm[];
    float* pri = sm;
    float* logits = pri + 19584;
    float* probs = logits + 1152;
    float* red = probs + 1152;
    __shared__ float wb[8];
    __shared__ float sbuf[17];

    int c = blockIdx.x, b = blockIdx.y, t = threadIdx.x;
    int lane = t & 31, wid = t >> 5;

    const float4* gp4 = (const float4*)(g_pri + (c * NB + b) * 18432);
#pragma unroll
    for (int k = 0; k < 18; k++) {
        int j = t + k * 256;
        float4 v = gp4[j];
        int n = j >> 2, q = (j & 3) * 4;
        float* pp = pri + n * 17 + q;
        pp[0] = v.x; pp[1] = v.y; pp[2] = v.z; pp[3] = v.w;
    }
    for (int j = t; j < 1152; j += 256) logits[j] = 0.f;
    __syncthreads();

    int oo = t & 15, sl = t >> 4;

    for (int it = 0; it < 3; it++) {
        float inv;
        if (it == 0) {
            inv = 1.f / 1152.f;
        } else {
            float lm = -1e30f;
            for (int n = t; n < 1152; n += 256) lm = fmaxf(lm, logits[n]);
#pragma unroll
            for (int off = 16; off > 0; off >>= 1)
                lm = fmaxf(lm, __shfl_xor_sync(0xffffffffu, lm, off));
            if (lane == 0) wb[wid] = lm;
            __syncthreads();
            float m = wb[0];
#pragma unroll
            for (int k = 1; k < 8; k++) m = fmaxf(m, wb[k]);
            __syncthreads();

            float ls = 0.f;
            for (int n = t; n < 1152; n += 256) {
                float e = __expf(logits[n] - m);
                probs[n] = e;
                ls += e;
            }
#pragma unroll
            for (int off = 16; off > 0; off >>= 1)
                ls += __shfl_xor_sync(0xffffffffu, ls, off);
            if (lane == 0) wb[wid] = ls;
            __syncthreads();
            float Z = 0.f;
#pragma unroll
            for (int k = 0; k < 8; k++) Z += wb[k];
            inv = 1.f / Z;
        }

        float sp = 0.f;
        if (it == 0) {
            for (int n = sl; n < 1152; n += 16) sp += pri[n * 17 + oo];
        } else {
            for (int n = sl; n < 1152; n += 16)
                sp = fmaf(probs[n], pri[n * 17 + oo], sp);
        }
        red[t] = sp;
        __syncthreads();
        if (t < 16) {
            float s = 0.f;
#pragma unroll
            for (int k = 0; k < 16; k++) s += red[k * 16 + t];
            sbuf[t] = s * inv;
        }
        __syncthreads();
        if (t == 0) {
            float sn = 0.f;
#pragma unroll
            for (int o = 0; o < 16; o++) sn = fmaf(sbuf[o], sbuf[o], sn);
            sbuf[16] = sn / ((1.f + sn) * sqrtf(sn));
        }
        __syncthreads();
        float scale = sbuf[16];

        if (it < 2) {
            for (int n = t; n < 1152; n += 256) {
                const float* pp = pri + n * 17;
                float d = 0.f;
#pragma unroll
                for (int o = 0; o < 16; o++) d = fmaf(pp[o], sbuf[o], d);
                logits[n] += d * scale;
            }
        } else {
            if (t < 16) g_v[(c * NB + b) * 16 + t] = sbuf[t] * scale;
        }
        __syncthreads();
    }
}

// ---------------- K5: classes/argmax/mask + decoder MLP ----------------------
__global__ void __launch_bounds__(256) k_dec(
    const float* __restrict__ w1, const float* __restrict__ b1,
    const float* __restrict__ w2, const float* __restrict__ b2,
    const float* __restrict__ w3, const float* __restrict__ b3,
    float* __restrict__ out) {
    extern __shared__ float sm[];
    float* h1 = sm;
    float* h2 = sm + 4096;
    float* vcap = h2 + 8192;
    float* cl = vcap + 128;
    __shared__ int cls[8];

    int t = threadIdx.x;
    int b0 = blockIdx.x * 8;
    const int RECON_OFF = NB * NCLS;
    const int CLS_OFF = RECON_OFF + NB * 784;

    if (t < 80) {
        int bb = t / 10, c = t - bb * 10;
        const float* vp = g_v + (c * NB + b0 + bb) * 16;
        float sn = 0.f;
#pragma unroll
        for (int o = 0; o < 16; o++) sn = fmaf(vp[o], vp[o], sn);
        float nv = sqrtf(sn);
        cl[bb * 10 + c] = nv;
        out[CLS_OFF + (b0 + bb) * 10 + c] = nv;
    }
    __syncthreads();
    if (t < 8) {
        float m = -1e30f;
        int idx = 0;
        for (int c = 0; c < 10; c++) {
            float v = cl[t * 10 + c];
            if (v > m) { m = v; idx = c; }
        }
        cls[t] = idx;
    }
    __syncthreads();
    if (t < 80) {
        int bb = t / 10, c = t - bb * 10;
        out[(b0 + bb) * 10 + c] = (c == cls[bb]) ? 1.f : 0.f;
    }
    if (t < 128) {
        int bb = t >> 4, o = t & 15;
        vcap[t] = g_v[(cls[bb] * NB + b0 + bb) * 16 + o];
    }
    __syncthreads();

#pragma unroll
    for (int jj = 0; jj < 2; jj++) {
        int j = t + jj * 256;
        float a[8];
        float bv = b1[j];
#pragma unroll
        for (int bb = 0; bb < 8; bb++) a[bb] = bv;
#pragma unroll 1
        for (int bb = 0; bb < 8; bb++) {
            const float* wr = w1 + (cls[bb] * 16) * 512 + j;
#pragma unroll
            for (int o = 0; o < 16; o++)
                a[bb] = fmaf(vcap[bb * 16 + o], wr[o * 512], a[bb]);
        }
#pragma unroll
        for (int bb = 0; bb < 8; bb++)
            h1[bb * 512 + j] = a[bb] > 0.f ? a[bb] : 0.f;
    }
    __syncthreads();

#pragma unroll 1
    for (int jj = 0; jj < 4; jj++) {
        int j = t + jj * 256;
        float a[8];
        float bv = b2[j];
#pragma unroll
        for (int bb = 0; bb < 8; bb++) a[bb] = bv;
#pragma unroll 4
        for (int k = 0; k < 512; k++) {
            float wv = w2[k * 1024 + j];
#pragma unroll
            for (int bb = 0; bb < 8; bb++)
                a[bb] = fmaf(wv, h1[bb * 512 + k], a[bb]);
        }
#pragma unroll
        for (int bb = 0; bb < 8; bb++)
            h2[bb * 1024 + j] = a[bb] > 0.f ? a[bb] : 0.f;
    }
    __syncthreads();

#pragma unroll 1
    for (int j = t; j < 784; j += 256) {
        float a[8];
        float bv = b3[j];
#pragma unroll
        for (int bb = 0; bb < 8; bb++) a[bb] = bv;
#pragma unroll 4
        for (int k = 0; k < 1024; k++) {
            float wv = w3[k * 784 + j];
#pragma unroll
            for (int bb = 0; bb < 8; bb++)
                a[bb] = fmaf(wv, h2[bb * 1024 + k], a[bb]);
        }
#pragma unroll
        for (int bb = 0; bb < 8; bb++)
            out[RECON_OFF + (b0 + bb) * 784 + j] = 1.f / (1.f + expf(-a[bb]));
    }
}

// ---------------- launch -----------------------------------------------------
extern "C" void kernel_launch(void* const* d_in, const int* in_sizes, int n_in,
                              void* d_out, int out_size) {
    const float* x = (const float*)d_in[0];
    const float* conv1_w = (const float*)d_in[1];
    const float* conv1_b = (const float*)d_in[2];
    const float* prim_w = (const float*)d_in[3];
    const float* prim_b = (const float*)d_in[4];
    const float* route_w = (const float*)d_in[5];
    const float* dec_w1 = (const float*)d_in[6];
    const float* dec_b1 = (const float*)d_in[7];
    const float* dec_w2 = (const float*)d_in[8];
    const float* dec_b2 = (const float*)d_in[9];
    const float* dec_w3 = (const float*)d_in[10];
    const float* dec_b3 = (const float*)d_in[11];
    float* out = (float*)d_out;

    const int SM_ROUTE = 22144 * sizeof(float);
    const int SM_DEC = 12496 * sizeof(float);
    cudaFuncSetAttribute(k_conv2t, cudaFuncAttributeMaxDynamicSharedMemorySize,
                         SM_CONV2);
    cudaFuncSetAttribute(k_route, cudaFuncAttributeMaxDynamicSharedMemorySize,
                         SM_ROUTE);
    cudaFuncSetAttribute(k_dec, cudaFuncAttributeMaxDynamicSharedMemorySize,
                         SM_DEC);

    k_wsplit<<<(16 * 81 * 256) / 256, 256>>>(prim_w);
    k_conv1<<<NB, 256>>>(x, conv1_w, conv1_b);
    k_conv2t<<<128, 256, SM_CONV2>>>(prim_b);
    k_pri<<<dim3(144, 10), 256>>>(route_w);
    k_route<<<dim3(NCLS, NB), 256, SM_ROUTE>>>();
    k_dec<<<NB / 8, 256, SM_DEC>>>(dec_w1, dec_b1, dec_w2, dec_b2, dec_w3,
                                   dec_b3, out);
}

// round 17
// speedup vs baseline: 2.9020x; 1.1327x over previous
#include <cuda_runtime.h>
#include <cuda_fp16.h>
#include <math.h>

#define NB 512
#define NROUTE 1152
#define NCLS 10

// ---------------- scratch ----------------------------------------------------
__device__ float g_h[NB * 256 * 400];          // conv1 out [B,256,20,20]
__device__ unsigned g_wfrag[16 * 81 * 2048];   // frag-ordered fp16 weights (10.4MB)
__device__ float g_u[NB * NROUTE * 8];         // squashed primary caps
__device__ float g_pri[NCLS * NB * NROUTE * 16]; // priors [c][b][n][o]
__device__ float g_v[NCLS * NB * 16];          // routed outputs [C,B,16]

// ---------------- ptx helpers ------------------------------------------------
__device__ __forceinline__ unsigned smem_u32(const void* p) {
    unsigned a;
    asm("{ .reg .u64 t; cvta.to.shared.u64 t, %1; cvt.u32.u64 %0, t; }"
        : "=r"(a) : "l"(p));
    return a;
}
__device__ __forceinline__ void ldsm_x4(unsigned* r, unsigned a) {
    asm volatile(
        "ldmatrix.sync.aligned.m8n8.x4.shared.b16 {%0,%1,%2,%3}, [%4];"
        : "=r"(r[0]), "=r"(r[1]), "=r"(r[2]), "=r"(r[3]) : "r"(a));
}
__device__ __forceinline__ void mma_f16(float* c, const unsigned* a,
                                        const unsigned* b) {
    asm volatile(
        "mma.sync.aligned.m16n8k16.row.col.f32.f16.f16.f32 "
        "{%0,%1,%2,%3}, {%4,%5,%6,%7}, {%8,%9}, {%0,%1,%2,%3};"
        : "+f"(c[0]), "+f"(c[1]), "+f"(c[2]), "+f"(c[3])
        : "r"(a[0]), "r"(a[1]), "r"(a[2]), "r"(a[3]), "r"(b[0]), "r"(b[1]));
}

// ---------------- K0: weights -> fragment-ordered gmem (fp16, single term) ---
// layout per (ct = chunk*81+tap): 2 stripes x 256 uint4 (nf 0-1 / nf 2-3).
// uint4 for thread t = {nf_a.b0, nf_a.b1, nf_b.b0, nf_b.b1}
// b0 = half2{W[k0],W[k0+1]}, b1 = half2{W[k0+8],W[k0+9]},
// k0 = (lane&3)*2, oc = wid*32 + nf*8 + lane/4, ic = chunk*16 + k.
__global__ void k_wsplit(const float* __restrict__ w) {
    int u = blockIdx.x * 256 + threadIdx.x;     // 16*81*256 = 331776 exact
    int t_ = u & 255;
    int ct = u >> 8;                             // 0..1295
    int chunk = ct / 81, tap = ct - chunk * 81;
    int lane = t_ & 31, wid5 = t_ >> 5;
    int k0 = (lane & 3) * 2, ncol = lane >> 2;
    uint4* outp = (uint4*)g_wfrag + (ct << 9) + t_;
#pragma unroll
    for (int np = 0; np < 2; np++) {
        unsigned hw[4];
#pragma unroll
        for (int w2 = 0; w2 < 2; w2++) {
            int oc = wid5 * 32 + (np * 2 + w2) * 8 + ncol;
#pragma unroll
            for (int rr = 0; rr < 2; rr++) {
                int ic = chunk * 16 + k0 + rr * 8;
                float v0 = w[(oc * 256 + ic) * 81 + tap];
                float v1 = w[(oc * 256 + ic + 1) * 81 + tap];
                __half h0 = __float2half_rn(v0), h1 = __float2half_rn(v1);
                hw[w2 * 2 + rr] = (unsigned)__half_as_ushort(h0) |
                                  ((unsigned)__half_as_ushort(h1) << 16);
            }
        }
        outp[np * 256] = make_uint4(hw[0], hw[1], hw[2], hw[3]);
    }
}

// ---------------- K1: conv1 9x9 s1 + relu ------------------------------------
__global__ void __launch_bounds__(256) k_conv1(const float* __restrict__ x,
                                               const float* __restrict__ w,
                                               const float* __restrict__ bias) {
    __shared__ float xs[784];
    int b = blockIdx.x, t = threadIdx.x;
    for (int j = t; j < 784; j += 256) xs[j] = x[b * 784 + j];
    __syncthreads();
    int oc = t;
    const float* wo = w + oc * 81;
    float bv = bias[oc];
    float* ho = g_h + (b * 256 + oc) * 400;
#pragma unroll 1
    for (int orow = 0; orow < 20; orow++) {
        float acc[20];
#pragma unroll
        for (int i = 0; i < 20; i++) acc[i] = 0.f;
#pragma unroll 1
        for (int ky = 0; ky < 9; ky++) {
            const float* xrp = xs + (orow + ky) * 28;
            float xr[28];
#pragma unroll
            for (int i = 0; i < 28; i++) xr[i] = xrp[i];
#pragma unroll
            for (int kx = 0; kx < 9; kx++) {
                float wv = wo[ky * 9 + kx];
#pragma unroll
                for (int ox = 0; ox < 20; ox++)
                    acc[ox] = fmaf(wv, xr[ox + kx], acc[ox]);
            }
        }
#pragma unroll
        for (int ox = 0; ox < 20; ox++) {
            float v = acc[ox] + bv;
            ho[orow * 20 + ox] = v > 0.f ? v : 0.f;
        }
    }
}

// ---------------- K2: tensor-core primary-caps conv + squash -----------------
// 4 batches per block, 128 blocks. 9 exact m16 slabs, all 256 oc.
// Single-term fp16 (both operands rounded): 36 MMA/iter, 2 LDG.128/iter.
// smem: hs[0,76800) rows R=b_l*400+px, stride 48, 16 ic fp16.
// epilogue reuses [0,149760) as Cs[144][260] f32
#define SM_CONV2 149760

__device__ __forceinline__ void stage_hs(char* smc, int b0, int ic0, int t) {
#pragma unroll 1
    for (int k = 0; k < 25; k++) {
        int e = t + k * 256;            // 0..6399 float4s
        int f4 = e % 100;
        int ic_l = (e / 100) & 15;
        int b_l = e / 1600;
        float4 v4 = *(const float4*)(g_h + (b0 + b_l) * 102400 +
                                     (ic0 + ic_l) * 400 + f4 * 4);
        int Rb = b_l * 400 + f4 * 4;
        float vv[4] = {v4.x, v4.y, v4.z, v4.w};
#pragma unroll
        for (int j = 0; j < 4; j++) {
            int off = (Rb + j) * 48 + ic_l * 2;
            *(__half*)(smc + off) = __float2half_rn(vv[j]);
        }
    }
}

__global__ void __launch_bounds__(256) k_conv2t(const float* __restrict__ bias) {
    extern __shared__ char smc[];
    const unsigned sbase = smem_u32(smc);
    int t = threadIdx.x, lane = t & 31, wid = t >> 5;
    int b0 = blockIdx.x * 4;

    float acc[9][4][4];
#pragma unroll
    for (int s9 = 0; s9 < 9; s9++)
#pragma unroll
        for (int nf = 0; nf < 4; nf++)
#pragma unroll
            for (int i = 0; i < 4; i++) acc[s9][nf][i] = 0.f;

    // per-lane ldmatrix row base offsets (bytes) per m16 slab
    int slabR[9];
    {
        int pl = (lane & 7) + ((lane >> 3) & 1) * 8;
        int badd = ((lane >> 4) & 1) * 16;
#pragma unroll
        for (int s9 = 0; s9 < 9; s9++) {
            int p = s9 * 16 + pl;
            int bl = p / 36, s = p % 36, r = s / 6, ox = s % 6;
            slabR[s9] = (bl * 400 + 40 * r + 2 * ox) * 48 + badd;
        }
    }

#pragma unroll 1
    for (int chunk = 0; chunk < 16; chunk++) {
        __syncthreads();
        stage_hs(smc, b0, chunk * 16, t);
        __syncthreads();
        const uint4* wfc = (const uint4*)g_wfrag + ((chunk * 81) << 9) + t;
#pragma unroll 3
        for (int tap = 0; tap < 81; tap++) {
            uint4 f0 = __ldg(wfc);
            uint4 f1 = __ldg(wfc + 256);
            wfc += 512;
            unsigned bh[4][2] = {{f0.x, f0.y}, {f0.z, f0.w},
                                 {f1.x, f1.y}, {f1.z, f1.w}};
            int ky = tap / 9, kx = tap - ky * 9;
            int delta = (20 * ky + kx) * 48;
            // slab-triples: same-acc reuse distance 12 MMAs
#pragma unroll
            for (int t3 = 0; t3 < 3; t3++) {
                unsigned ah[3][4];
#pragma unroll
                for (int sl = 0; sl < 3; sl++)
                    ldsm_x4(ah[sl], sbase + slabR[t3 * 3 + sl] + delta);
#pragma unroll
                for (int sl = 0; sl < 3; sl++)
#pragma unroll
                    for (int nf = 0; nf < 4; nf++)
                        mma_f16(acc[t3 * 3 + sl][nf], ah[sl], bh[nf]);
            }
        }
    }

    // epilogue: bias + store to smem Cs[144][260]
    __syncthreads();
    float* Cs = (float*)smc;
    int grp = lane >> 2, q = lane & 3;
    int ocb = wid * 32 + 2 * q;
    float bset[4][2];
#pragma unroll
    for (int nf = 0; nf < 4; nf++) {
        bset[nf][0] = bias[ocb + nf * 8];
        bset[nf][1] = bias[ocb + nf * 8 + 1];
    }
#pragma unroll
    for (int s9 = 0; s9 < 9; s9++) {
        int p0 = s9 * 16 + grp;
#pragma unroll
        for (int nf = 0; nf < 4; nf++) {
            int oc = ocb + nf * 8;
            Cs[p0 * 260 + oc] = acc[s9][nf][0] + bset[nf][0];
            Cs[p0 * 260 + oc + 1] = acc[s9][nf][1] + bset[nf][1];
            Cs[(p0 + 8) * 260 + oc] = acc[s9][nf][2] + bset[nf][0];
            Cs[(p0 + 8) * 260 + oc + 1] = acc[s9][nf][3] + bset[nf][1];
        }
    }
    __syncthreads();

    // fused capsule gather + squash -> g_u (4 batches * 1152 caps)
#pragma unroll 1
    for (int k = 0; k < 18; k++) {
        int cap = t + k * 256;
        int b_l = cap / 1152;
        int n = cap - b_l * 1152;
        int c = n / 36, s = n - c * 36;
        const float* row = Cs + (b_l * 36 + s) * 260 + c;
        float tv[8], sn = 0.f;
#pragma unroll
        for (int g = 0; g < 8; g++) {
            tv[g] = row[g * 32];
            sn = fmaf(tv[g], tv[g], sn);
        }
        float sc = sn / ((1.f + sn) * sqrtf(sn));
        float* up = g_u + ((b0 + b_l) * 1152 + n) * 8;
#pragma unroll
        for (int g = 0; g < 8; g++) up[g] = tv[g] * sc;
    }
}

// ---------------- K3: priors GEMM -> g_pri -----------------------------------
__global__ void __launch_bounds__(256) k_pri(const float* __restrict__ rw_all) {
    __shared__ float ws[1024];
    __shared__ float us[8192];
    int t = threadIdx.x, lane = t & 31, w = t >> 5;
    int c = blockIdx.y, n0 = blockIdx.x * 8;

    {
        const float4* rw4 = (const float4*)rw_all;
        int dn = t >> 5, idx4 = t & 31;
        ((float4*)ws)[t] = rw4[c * 36864 + (n0 + dn) * 32 + idx4];
    }
    __syncthreads();

    int o = (lane & 7) * 2, bh = lane >> 3;
    float wr0[8], wr1[8];
#pragma unroll
    for (int i = 0; i < 8; i++) {
        wr0[i] = ws[w * 128 + i * 16 + o];
        wr1[i] = ws[w * 128 + i * 16 + o + 1];
    }

#pragma unroll 1
    for (int ch = 0; ch < 4; ch++) {
        int bchunk = ch * 128;
        __syncthreads();
        const float4* u4 = (const float4*)g_u;
#pragma unroll
        for (int k = 0; k < 8; k++) {
            int j = t + k * 256;
            int bl = j >> 4, r4 = j & 15;
            ((float4*)us)[j] = u4[(bchunk + bl) * 2304 + n0 * 2 + r4];
        }
        __syncthreads();
#pragma unroll 2
        for (int kk = 0; kk < 32; kk++) {
            int bl = kk * 4 + bh;
            const float* up = us + bl * 64 + w * 8;
            float4 ua = *(const float4*)up;
            float4 ub = *(const float4*)(up + 4);
            float a0 = ua.x * wr0[0] + ua.y * wr0[1] + ua.z * wr0[2] +
                       ua.w * wr0[3] + ub.x * wr0[4] + ub.y * wr0[5] +
                       ub.z * wr0[6] + ub.w * wr0[7];
            float a1 = ua.x * wr1[0] + ua.y * wr1[1] + ua.z * wr1[2] +
                       ua.w * wr1[3] + ub.x * wr1[4] + ub.y * wr1[5] +
                       ub.z * wr1[6] + ub.w * wr1[7];
            *(float2*)(g_pri + ((c * NB + bchunk + bl) * NROUTE + n0 + w) * 16 +
                       o) = make_float2(a0, a1);
        }
    }
}

// ---------------- K4: 3-iter dynamic routing ---------------------------------
__global__ void __launch_bounds__(256) k_route(void) {
    extern __shared__ float sm[];
    float* pri = sm;
    float* logits = pri + 19584;
    float* probs = logits + 1152;
    float* red = probs + 1152;
    __shared__ float wb[8];
    __shared__ float sbuf[17];

    int c = blockIdx.x, b = blockIdx.y, t = threadIdx.x;
    int lane = t & 31, wid = t >> 5;

    const float4* gp4 = (const float4*)(g_pri + (c * NB + b) * 18432);
#pragma unroll
    for (int k = 0; k < 18; k++) {
        int j = t + k * 256;
        float4 v = gp4[j];
        int n = j >> 2, q = (j & 3) * 4;
        float* pp = pri + n * 17 + q;
        pp[0] = v.x; pp[1] = v.y; pp[2] = v.z; pp[3] = v.w;
    }
    for (int j = t; j < 1152; j += 256) logits[j] = 0.f;
    __syncthreads();

    int oo = t & 15, sl = t >> 4;

    for (int it = 0; it < 3; it++) {
        float inv;
        if (it == 0) {
            inv = 1.f / 1152.f;
        } else {
            float lm = -1e30f;
            for (int n = t; n < 1152; n += 256) lm = fmaxf(lm, logits[n]);
#pragma unroll
            for (int off = 16; off > 0; off >>= 1)
                lm = fmaxf(lm, __shfl_xor_sync(0xffffffffu, lm, off));
            if (lane == 0) wb[wid] = lm;
            __syncthreads();
            float m = wb[0];
#pragma unroll
            for (int k = 1; k < 8; k++) m = fmaxf(m, wb[k]);
            __syncthreads();

            float ls = 0.f;
            for (int n = t; n < 1152; n += 256) {
                float e = __expf(logits[n] - m);
                probs[n] = e;
                ls += e;
            }
#pragma unroll
            for (int off = 16; off > 0; off >>= 1)
                ls += __shfl_xor_sync(0xffffffffu, ls, off);
            if (lane == 0) wb[wid] = ls;
            __syncthreads();
            float Z = 0.f;
#pragma unroll
            for (int k = 0; k < 8; k++) Z += wb[k];
            inv = 1.f / Z;
        }

        float sp = 0.f;
        if (it == 0) {
            for (int n = sl; n < 1152; n += 16) sp += pri[n * 17 + oo];
        } else {
            for (int n = sl; n < 1152; n += 16)
                sp = fmaf(probs[n], pri[n * 17 + oo], sp);
        }
        red[t] = sp;
        __syncthreads();
        if (t < 16) {
            float s = 0.f;
#pragma unroll
            for (int k = 0; k < 16; k++) s += red[k * 16 + t];
            sbuf[t] = s * inv;
        }
        __syncthreads();
        if (t == 0) {
            float sn = 0.f;
#pragma unroll
            for (int o = 0; o < 16; o++) sn = fmaf(sbuf[o], sbuf[o], sn);
            sbuf[16] = sn / ((1.f + sn) * sqrtf(sn));
        }
        __syncthreads();
        float scale = sbuf[16];

        if (it < 2) {
            for (int n = t; n < 1152; n += 256) {
                const float* pp = pri + n * 17;
                float d = 0.f;
#pragma unroll
                for (int o = 0; o < 16; o++) d = fmaf(pp[o], sbuf[o], d);
                logits[n] += d * scale;
            }
        } else {
            if (t < 16) g_v[(c * NB + b) * 16 + t] = sbuf[t] * scale;
        }
        __syncthreads();
    }
}

// ---------------- K5: classes/argmax/mask + decoder MLP ----------------------
__global__ void __launch_bounds__(256) k_dec(
    const float* __restrict__ w1, const float* __restrict__ b1,
    const float* __restrict__ w2, const float* __restrict__ b2,
    const float* __restrict__ w3, const float* __restrict__ b3,
    float* __restrict__ out) {
    extern __shared__ float sm[];
    float* h1 = sm;
    float* h2 = sm + 4096;
    float* vcap = h2 + 8192;
    float* cl = vcap + 128;
    __shared__ int cls[8];

    int t = threadIdx.x;
    int b0 = blockIdx.x * 8;
    const int RECON_OFF = NB * NCLS;
    const int CLS_OFF = RECON_OFF + NB * 784;

    if (t < 80) {
        int bb = t / 10, c = t - bb * 10;
        const float* vp = g_v + (c * NB + b0 + bb) * 16;
        float sn = 0.f;
#pragma unroll
        for (int o = 0; o < 16; o++) sn = fmaf(vp[o], vp[o], sn);
        float nv = sqrtf(sn);
        cl[bb * 10 + c] = nv;
        out[CLS_OFF + (b0 + bb) * 10 + c] = nv;
    }
    __syncthreads();
    if (t < 8) {
        float m = -1e30f;
        int idx = 0;
        for (int c = 0; c < 10; c++) {
            float v = cl[t * 10 + c];
            if (v > m) { m = v; idx = c; }
        }
        cls[t] = idx;
    }
    __syncthreads();
    if (t < 80) {
        int bb = t / 10, c = t - bb * 10;
        out[(b0 + bb) * 10 + c] = (c == cls[bb]) ? 1.f : 0.f;
    }
    if (t < 128) {
        int bb = t >> 4, o = t & 15;
        vcap[t] = g_v[(cls[bb] * NB + b0 + bb) * 16 + o];
    }
    __syncthreads();

#pragma unroll
    for (int jj = 0; jj < 2; jj++) {
        int j = t + jj * 256;
        float a[8];
        float bv = b1[j];
#pragma unroll
        for (int bb = 0; bb < 8; bb++) a[bb] = bv;
#pragma unroll 1
        for (int bb = 0; bb < 8; bb++) {
            const float* wr = w1 + (cls[bb] * 16) * 512 + j;
#pragma unroll
            for (int o = 0; o < 16; o++)
                a[bb] = fmaf(vcap[bb * 16 + o], wr[o * 512], a[bb]);
        }
#pragma unroll
        for (int bb = 0; bb < 8; bb++)
            h1[bb * 512 + j] = a[bb] > 0.f ? a[bb] : 0.f;
    }
    __syncthreads();

#pragma unroll 1
    for (int jj = 0; jj < 4; jj++) {
        int j = t + jj * 256;
        float a[8];
        float bv = b2[j];
#pragma unroll
        for (int bb = 0; bb < 8; bb++) a[bb] = bv;
#pragma unroll 4
        for (int k = 0; k < 512; k++) {
            float wv = w2[k * 1024 + j];
#pragma unroll
            for (int bb = 0; bb < 8; bb++)
                a[bb] = fmaf(wv, h1[bb * 512 + k], a[bb]);
        }
#pragma unroll
        for (int bb = 0; bb < 8; bb++)
            h2[bb * 1024 + j] = a[bb] > 0.f ? a[bb] : 0.f;
    }
    __syncthreads();

#pragma unroll 1
    for (int j = t; j < 784; j += 256) {
        float a[8];
        float bv = b3[j];
#pragma unroll
        for (int bb = 0; bb < 8; bb++) a[bb] = bv;
#pragma unroll 4
        for (int k = 0; k < 1024; k++) {
            float wv = w3[k * 784 + j];
#pragma unroll
            for (int bb = 0; bb < 8; bb++)
                a[bb] = fmaf(wv, h2[bb * 1024 + k], a[bb]);
        }
#pragma unroll
        for (int bb = 0; bb < 8; bb++)
            out[RECON_OFF + (b0 + bb) * 784 + j] = 1.f / (1.f + expf(-a[bb]));
    }
}

// ---------------- launch -----------------------------------------------------
extern "C" void kernel_launch(void* const* d_in, const int* in_sizes, int n_in,
                              void* d_out, int out_size) {
    const float* x = (const float*)d_in[0];
    const float* conv1_w = (const float*)d_in[1];
    const float* conv1_b = (const float*)d_in[2];
    const float* prim_w = (const float*)d_in[3];
    const float* prim_b = (const float*)d_in[4];
    const float* route_w = (const float*)d_in[5];
    const float* dec_w1 = (const float*)d_in[6];
    const float* dec_b1 = (const float*)d_in[7];
    const float* dec_w2 = (const float*)d_in[8];
    const float* dec_b2 = (const float*)d_in[9];
    const float* dec_w3 = (const float*)d_in[10];
    const float* dec_b3 = (const float*)d_in[11];
    float* out = (float*)d_out;

    const int SM_ROUTE = 22144 * sizeof(float);
    const int SM_DEC = 12496 * sizeof(float);
    cudaFuncSetAttribute(k_conv2t, cudaFuncAttributeMaxDynamicSharedMemorySize,
                         SM_CONV2);
    cudaFuncSetAttribute(k_route, cudaFuncAttributeMaxDynamicSharedMemorySize,
                         SM_ROUTE);
    cudaFuncSetAttribute(k_dec, cudaFuncAttributeMaxDynamicSharedMemorySize,
                         SM_DEC);

    k_wsplit<<<(16 * 81 * 256) / 256, 256>>>(prim_w);
    k_conv1<<<NB, 256>>>(x, conv1_w, conv1_b);
    k_conv2t<<<128, 256, SM_CONV2>>>(prim_b);
    k_pri<<<dim3(144, 10), 256>>>(route_w);
    k_route<<<dim3(NCLS, NB), 256, SM_ROUTE>>>();
    k_dec<<<NB / 8, 256, SM_DEC>>>(dec_w1, dec_b1, dec_w2, dec_b2, dec_w3,
                                   dec_b3, out);
}